// round 14
// baseline (speedup 1.0000x reference)
#include <cuda_runtime.h>
#include <cuda_bf16.h>
#include <math.h>
#include <stdint.h>

// Problem constants (B=8, L=2048, D=512, K=4, m=256)
#define Bn 8
#define Ln 2048
#define Dn 512
#define Mf 256
#define KLn 8192
#define ROWS_Q 16384
#define ROWS_K 65536

// ===========================================================================
// Canonical fragment layouts (u32 = bf16 pair, low16 = even k):
//  A: element (row r, kpair kp):  g=r>>4, b=(r&15)>>3, gid=r&7,
//     s=kp>>3, tig=kp&3, hi=(kp>>2)&1, j=b+2*hi
//     u32 index = ((g*SA + s)*32 + gid*4 + tig)*4 + j          (SA = K/16)
//  B: element (kp, col n): s=kp>>3, tig=kp&3, j=(kp>>2)&1, h=n>>3, gid=n&7
//     u32 index = ((s*(N/8) + h)*32 + gid*4 + tig)*2 + j
// ===========================================================================

__device__ unsigned g_cA_h[(size_t)(ROWS_Q/16)*32*128];      // content A canon
__device__ unsigned g_cA_l[(size_t)(ROWS_Q/16)*32*128];
__device__ unsigned g_sA_h[(size_t)(ROWS_K/16)*32*128];      // style A canon
__device__ unsigned g_sA_l[(size_t)(ROWS_K/16)*32*128];
__device__ unsigned g_wB_h[(size_t)32*32*64];                // W B canon
__device__ unsigned g_wB_l[(size_t)32*32*64];
__device__ unsigned g_spB_h[(size_t)Bn*512*64*64];           // style B canon
__device__ unsigned g_spB_l[(size_t)Bn*512*64*64];
__device__ unsigned g_pq_h[(size_t)ROWS_Q*(Mf/2)];           // phi_q std
__device__ unsigned g_pq_l[(size_t)ROWS_Q*(Mf/2)];
__device__ unsigned g_pqc_h[(size_t)(ROWS_Q/16)*16*128];     // phi_q A canon
__device__ unsigned g_pqc_l[(size_t)(ROWS_Q/16)*16*128];
__device__ unsigned g_pk_h[(size_t)ROWS_K*(Mf/2)];           // phi_k std
__device__ unsigned g_pk_l[(size_t)ROWS_K*(Mf/2)];
__device__ unsigned g_pkT_h[(size_t)Bn*16*512*128];          // phi_k^T A canon
__device__ unsigned g_pkT_l[(size_t)Bn*16*512*128];
__device__ unsigned g_sB_h[(size_t)Bn*16*64*64];             // S B canon
__device__ unsigned g_sB_l[(size_t)Bn*16*64*64];
__device__ float g_S[(size_t)Bn*Mf*Dn];
__device__ float g_Z[Bn*Mf];
__device__ float g_den[ROWS_Q];
__device__ float g_sq_q[ROWS_Q];
__device__ float g_sq_k[ROWS_K];

__device__ __constant__ float PROJ_SCALE = 0.21022410381342864f;  // 512^-0.25
__device__ __constant__ float SQ_SCALE   = 0.022097086912079608f; // 1/(2*sqrt(512))
__device__ __constant__ float RSQ_M      = 0.0625f;               // 256^-0.5

// ---------------- helpers ----------------------------------------------------
__device__ __forceinline__ uint32_t smem_addr(const void* p) {
    uint32_t a;
    asm("{ .reg .u64 t; cvta.to.shared.u64 t, %1; cvt.u32.u64 %0, t; }" : "=r"(a) : "l"(p));
    return a;
}
__device__ __forceinline__ void split1(float x, unsigned short& h, unsigned short& l) {
    __nv_bfloat16 hb = __float2bfloat16_rn(x);
    h = __bfloat16_as_ushort(hb);
    l = __bfloat16_as_ushort(__float2bfloat16_rn(x - __bfloat162float(hb)));
}
__device__ __forceinline__ float bfu(unsigned short u) {
    return __bfloat162float(__ushort_as_bfloat16(u));
}
__device__ __forceinline__ void packpair(float a, float b, unsigned& h, unsigned& l) {
    unsigned short ha, la, hb, lb;
    split1(a, ha, la); split1(b, hb, lb);
    h = (unsigned)ha | ((unsigned)hb << 16);
    l = (unsigned)la | ((unsigned)lb << 16);
}
__device__ __forceinline__ void cp16(uint32_t d, const void* g) {
    asm volatile("cp.async.cg.shared.global [%0], [%1], 16;" :: "r"(d), "l"(g));
}
__device__ __forceinline__ void mma_bf16(float c[4], const unsigned a[4], const unsigned b[2]) {
    asm volatile(
        "mma.sync.aligned.m16n8k16.row.col.f32.bf16.bf16.f32 "
        "{%0,%1,%2,%3}, {%4,%5,%6,%7}, {%8,%9}, {%0,%1,%2,%3};\n"
        : "+f"(c[0]), "+f"(c[1]), "+f"(c[2]), "+f"(c[3])
        : "r"(a[0]), "r"(a[1]), "r"(a[2]), "r"(a[3]), "r"(b[0]), "r"(b[1]));
}

// ---------------------------------------------------------------------------
// rowsumsq + canonical-A pack.  grid = rows/16, block = 256.
// ---------------------------------------------------------------------------
__global__ void rowsumsq_pack(const float* __restrict__ X, float* __restrict__ sq,
                              unsigned* __restrict__ OH, unsigned* __restrict__ OL)
{
    int g = blockIdx.x;
    int w = threadIdx.x >> 5;
    int s = threadIdx.x & 31;
    int r0 = g * 16 + w;
    int r1 = r0 + 8;

    float f0[16], f1[16];
    {
        const float4* p0 = (const float4*)(X + (long)r0 * Dn + s * 16);
        const float4* p1 = (const float4*)(X + (long)r1 * Dn + s * 16);
        #pragma unroll
        for (int i = 0; i < 4; i++) {
            float4 v = p0[i];
            f0[4*i] = v.x; f0[4*i+1] = v.y; f0[4*i+2] = v.z; f0[4*i+3] = v.w;
            v = p1[i];
            f1[4*i] = v.x; f1[4*i+1] = v.y; f1[4*i+2] = v.z; f1[4*i+3] = v.w;
        }
    }
    float s0 = 0.f, s1 = 0.f;
    #pragma unroll
    for (int i = 0; i < 16; i++) { s0 += f0[i]*f0[i]; s1 += f1[i]*f1[i]; }
    #pragma unroll
    for (int o = 16; o; o >>= 1) {
        s0 += __shfl_xor_sync(0xffffffffu, s0, o);
        s1 += __shfl_xor_sync(0xffffffffu, s1, o);
    }
    if (s == 0) { sq[r0] = s0 * SQ_SCALE; sq[r1] = s1 * SQ_SCALE; }

    unsigned wh[16], wl[16];
    #pragma unroll
    for (int tig = 0; tig < 4; tig++) {
        #pragma unroll
        for (int q = 0; q < 4; q++) {
            int t = tig + 4 * (q >> 1);
            const float* f = (q & 1) ? f1 : f0;
            packpair(f[2*t], f[2*t+1], wh[tig*4+q], wl[tig*4+q]);
        }
    }
    long base = (((long)g * 32 + s) * 32 + w * 4) * 4;
    #pragma unroll
    for (int i = 0; i < 4; i++) {
        *(uint4*)(OH + base + i * 4) = make_uint4(wh[4*i], wh[4*i+1], wh[4*i+2], wh[4*i+3]);
        *(uint4*)(OL + base + i * 4) = make_uint4(wl[4*i], wl[4*i+1], wl[4*i+2], wl[4*i+3]);
    }
}

// ---------------------------------------------------------------------------
// styleB_pack: canonical-B pack of style with coalesced reads AND writes.
// ---------------------------------------------------------------------------
__global__ void styleB_pack(const float* __restrict__ X,
                            unsigned* __restrict__ BH, unsigned* __restrict__ BL)
{
    int g = blockIdx.x;
    const float* tb = X + (long)g * 16 * Dn;
    int bb = g >> 9;
    long sL = g & 511;
    #pragma unroll
    for (int rep = 0; rep < 2; rep++) {
        int n = threadIdx.x + rep * 256;
        int hB = n >> 3, gidn = n & 7;
        unsigned bh[8], bl[8];
        #pragma unroll
        for (int t = 0; t < 8; t++)
            packpair(tb[(long)(2*t) * Dn + n], tb[(long)(2*t+1) * Dn + n], bh[t], bl[t]);
        long o = (long)bb * (512L*64*64) + ((sL * 64 + hB) * 32 + gidn * 4) * 2;
        *(uint4*)(BH + o)     = make_uint4(bh[0], bh[4], bh[1], bh[5]);
        *(uint4*)(BH + o + 4) = make_uint4(bh[2], bh[6], bh[3], bh[7]);
        *(uint4*)(BL + o)     = make_uint4(bl[0], bl[4], bl[1], bl[5]);
        *(uint4*)(BL + o + 4) = make_uint4(bl[2], bl[6], bl[3], bl[7]);
    }
}

// ---------------------------------------------------------------------------
// Canonical-B pack from fp32 [K][N] (batched). Used for W and S.
// ---------------------------------------------------------------------------
__global__ void packB_canon(const float* __restrict__ src,
                            unsigned* __restrict__ dh, unsigned* __restrict__ dl,
                            int K, int N, long srcBatch, long dstBatchU2)
{
    long blk = (long)blockIdx.x * 8 + (threadIdx.x >> 5);
    int lane = threadIdx.x & 31;
    int gid = lane >> 2, tig = lane & 3;
    long perBatch = (long)(K / 16) * (N / 8);
    int bb = (int)(blk / perBatch);
    long rem = blk % perBatch;
    int s = (int)(rem / (N / 8));
    int h = (int)(rem % (N / 8));
    int n = h * 8 + gid;
    const float* sb = src + (long)bb * srcBatch;
    unsigned h0, l0, h1, l1;
    {
        int r = 16 * s + 2 * tig;
        packpair(sb[(long)r * N + n], sb[(long)(r + 1) * N + n], h0, l0);
        packpair(sb[(long)(r + 8) * N + n], sb[(long)(r + 9) * N + n], h1, l1);
    }
    long u2 = (long)bb * dstBatchU2 + ((long)s * (N / 8) + h) * 32 + lane;
    ((uint2*)dh)[u2] = make_uint2(h0, h1);
    ((uint2*)dl)[u2] = make_uint2(l0, l1);
}

// ---------------------------------------------------------------------------
// transpose-pack phi_k std -> canonical-A [b][m][kl] (SA=512), with fused Z.
// ---------------------------------------------------------------------------
__global__ void transpack(const unsigned* __restrict__ sh_, const unsigned* __restrict__ sl_,
                          unsigned* __restrict__ dh, unsigned* __restrict__ dl,
                          float* __restrict__ Z)
{
    __shared__ unsigned Th[64][33], Tl[64][33];
    int tk = blockIdx.x, tm = blockIdx.y, bb = blockIdx.z;
    const unsigned* sh = sh_ + ((long)bb * KLn + tk * 64) * (Mf/2) + tm * 32;
    const unsigned* sl = sl_ + ((long)bb * KLn + tk * 64) * (Mf/2) + tm * 32;
    int r = threadIdx.x >> 3, c4 = (threadIdx.x & 7) * 4;
    {
        uint4 v = *(const uint4*)(sh + (long)r * (Mf/2) + c4);
        Th[r][c4] = v.x; Th[r][c4+1] = v.y; Th[r][c4+2] = v.z; Th[r][c4+3] = v.w;
        v = *(const uint4*)(sh + (long)(r + 32) * (Mf/2) + c4);
        Th[r+32][c4] = v.x; Th[r+32][c4+1] = v.y; Th[r+32][c4+2] = v.z; Th[r+32][c4+3] = v.w;
        v = *(const uint4*)(sl + (long)r * (Mf/2) + c4);
        Tl[r][c4] = v.x; Tl[r][c4+1] = v.y; Tl[r][c4+2] = v.z; Tl[r][c4+3] = v.w;
        v = *(const uint4*)(sl + (long)(r + 32) * (Mf/2) + c4);
        Tl[r+32][c4] = v.x; Tl[r+32][c4+1] = v.y; Tl[r+32][c4+2] = v.z; Tl[r+32][c4+3] = v.w;
    }
    __syncthreads();
    int m = threadIdx.x >> 2;
    int kj = (threadIdx.x & 3) * 8;
    int mp = m >> 1, pm = m & 1;
    unsigned oh[8], ol[8];
    float zsum = 0.f;
    #pragma unroll
    for (int j = 0; j < 8; j++) {
        int klp = kj + j;
        unsigned t0 = Th[2*klp][mp],   t1 = Th[2*klp+1][mp];
        unsigned u0 = Tl[2*klp][mp],   u1 = Tl[2*klp+1][mp];
        unsigned e0 = pm ? (t0 >> 16) : (t0 & 0xffff);
        unsigned e1 = pm ? (t1 >> 16) : (t1 & 0xffff);
        oh[j] = e0 | (e1 << 16);
        unsigned f0 = pm ? (u0 >> 16) : (u0 & 0xffff);
        unsigned f1 = pm ? (u1 >> 16) : (u1 & 0xffff);
        ol[j] = f0 | (f1 << 16);
        zsum += bfu((unsigned short)e0) + bfu((unsigned short)e1)
              + bfu((unsigned short)f0) + bfu((unsigned short)f1);
    }
    int mg = tm * 64 + m;
    atomicAdd(&Z[bb * Mf + mg], zsum);
    int g = mg >> 4, b_ = (mg & 15) >> 3, gidw = mg & 7;
    int sS = (tk * 32 + kj) >> 3;
    long base = (long)bb * (16L * 512 * 128) + (((long)g * 512 + sS) * 32 + gidw * 4) * 4;
    #pragma unroll
    for (int j = 0; j < 8; j++) {
        int tig = j & 3, hi = j >> 2;
        long a = base + tig * 4 + b_ + 2 * hi;
        dh[a] = oh[j]; dl[a] = ol[j];
    }
}

__global__ void zero_kernel(float* __restrict__ S, float* __restrict__ Z)
{
    long i = (long)blockIdx.x * 256 + threadIdx.x;
    if (i < (long)Bn * Mf * Dn) S[i] = 0.f;
    if (i < Bn * Mf)            Z[i] = 0.f;
}

// ---------------------------------------------------------------------------
// Canonical-layout bf16x2-compensated GEMM, BM=128 BN=128 BK=32,
// 4 warps (2 wm x 2 wn), warp tile 64x64, 3-stage cp.async pipeline.
//  Stage (u32): AH 0..2047 | AL 2048..4095 | BH 4096..6143 | BL 6144..8191
// ---------------------------------------------------------------------------
#define STG_U32 8192
#define N_STAGES 3
#define SMEM_BYTES (N_STAGES * STG_U32 * 4)

template<int EPI>
__global__ void __launch_bounds__(128)
tc_gemm(const unsigned* __restrict__ Ah, const unsigned* __restrict__ Al,
        const unsigned* __restrict__ Bh, const unsigned* __restrict__ Bl,
        float* __restrict__ C, int Ksz, int SA, int Nt, int ldc, int SAout,
        long batchA, long batchB, long batchC, int splitK,
        const float* __restrict__ sq,
        unsigned* __restrict__ OH, unsigned* __restrict__ OL,
        unsigned* __restrict__ OH2, unsigned* __restrict__ OL2,
        const float* __restrict__ den, const float* __restrict__ content,
        float* __restrict__ out2)
{
    extern __shared__ __align__(16) unsigned sm[];

    int bz = blockIdx.z;
    int b  = bz / splitK;
    int sp = bz % splitK;
    int sBeg = sp * (Ksz / 16);

    const unsigned* Agh = Ah + (long)b * batchA;
    const unsigned* Agl = Al + (long)b * batchA;
    const unsigned* Bgh = Bh + (long)b * batchB;
    const unsigned* Bgl = Bl + (long)b * batchB;

    int rowBlk = blockIdx.y * 128;
    int colBlk = blockIdx.x * 128;
    int gA = rowBlk >> 4;
    int hA = colBlk >> 3;
    int tid = threadIdx.x, wid = tid >> 5, lane = tid & 31;
    int gid = lane >> 2, tig = lane & 3;
    int wm = wid >> 1, wn = wid & 1;

    auto loadStage = [&](int t, int st) {
        unsigned* base = sm + st * STG_U32;
        int s0 = sBeg + 2 * t;
        // A: 16 blocks of 128 u32 (gl 0..7 x sl 0..1); 8 thr/block, 16 u32 each
        {
            int blk = tid >> 3;
            int gl = blk >> 1, sl = blk & 1;
            int inner = (tid & 7) * 16;
            long src = (((long)(gA + gl)) * SA + (s0 + sl)) * 128 + inner;
            uint32_t dst = smem_addr(base + blk * 128 + inner);
            cp16(dst,      Agh + src);      cp16(dst + 16, Agh + src + 4);
            cp16(dst + 32, Agh + src + 8);  cp16(dst + 48, Agh + src + 12);
            cp16(dst + 8192,      Agl + src);      cp16(dst + 8192 + 16, Agl + src + 4);
            cp16(dst + 8192 + 32, Agl + src + 8);  cp16(dst + 8192 + 48, Agl + src + 12);
        }
        // B: 32 blocks of 64 u32 (sl 0..1 x hl 0..15); 4 thr/block, 16 u32 each
        {
            int blk = tid >> 2;
            int sl = blk >> 4, hl = blk & 15;
            int inner = (tid & 3) * 16;
            long src = ((long)(s0 + sl)) * (Nt / 8) * 64 + (long)(hA + hl) * 64 + inner;
            uint32_t dst = smem_addr(base + 4096 + blk * 64 + inner);
            cp16(dst,      Bgh + src);      cp16(dst + 16, Bgh + src + 4);
            cp16(dst + 32, Bgh + src + 8);  cp16(dst + 48, Bgh + src + 12);
            cp16(dst + 8192,      Bgl + src);      cp16(dst + 8192 + 16, Bgl + src + 4);
            cp16(dst + 8192 + 32, Bgl + src + 8);  cp16(dst + 8192 + 48, Bgl + src + 12);
        }
    };

    float acc[4][8][4] = {};
    int nT = Ksz / 32;

    loadStage(0, 0);
    asm volatile("cp.async.commit_group;" ::: "memory");
    loadStage(1, 1);
    asm volatile("cp.async.commit_group;" ::: "memory");

    for (int t = 0; t < nT; t++) {
        asm volatile("cp.async.wait_group 1;" ::: "memory");
        __syncthreads();

        if (t + 2 < nT) {
            loadStage(t + 2, (t + 2) % N_STAGES);
            asm volatile("cp.async.commit_group;" ::: "memory");
        } else {
            asm volatile("cp.async.commit_group;" ::: "memory");
        }

        unsigned* base = sm + (t % N_STAGES) * STG_U32;

        #pragma unroll
        for (int kk = 0; kk < 2; kk++) {
            unsigned afh[4][4], afl[4][4], bfh[8][2], bfl[8][2];
            #pragma unroll
            for (int mi = 0; mi < 4; mi++) {
                int off = ((wm * 4 + mi) * 2 + kk) * 128 + lane * 4;
                uint4 v = *(uint4*)(base + off);
                afh[mi][0] = v.x; afh[mi][1] = v.y; afh[mi][2] = v.z; afh[mi][3] = v.w;
                v = *(uint4*)(base + 2048 + off);
                afl[mi][0] = v.x; afl[mi][1] = v.y; afl[mi][2] = v.z; afl[mi][3] = v.w;
            }
            #pragma unroll
            for (int ni = 0; ni < 8; ni++) {
                int off = 4096 + (kk * 16 + wn * 8 + ni) * 64 + lane * 2;
                uint2 v = *(uint2*)(base + off);
                bfh[ni][0] = v.x; bfh[ni][1] = v.y;
                v = *(uint2*)(base + 2048 + off);
                bfl[ni][0] = v.x; bfl[ni][1] = v.y;
            }
            #pragma unroll
            for (int mi = 0; mi < 4; mi++)
                #pragma unroll
                for (int ni = 0; ni < 8; ni++) {
                    mma_bf16(acc[mi][ni], afl[mi], bfh[ni]);
                    mma_bf16(acc[mi][ni], afh[mi], bfl[ni]);
                    mma_bf16(acc[mi][ni], afh[mi], bfh[ni]);
                }
        }
    }
    asm volatile("cp.async.wait_group 0;" ::: "memory");

    // ---- epilogue ----
    float* Cb = C + (long)b * batchC;
    #pragma unroll
    for (int mi = 0; mi < 4; mi++) {
        #pragma unroll
        for (int ni = 0; ni < 8; ni++) {
            int r0 = rowBlk + wm * 64 + mi * 16 + gid;
            int c0 = colBlk + wn * 64 + ni * 8 + tig * 2;
            #pragma unroll
            for (int h = 0; h < 2; h++) {
                int r = r0 + h * 8;
                float v0 = acc[mi][ni][h * 2 + 0];
                float v1 = acc[mi][ni][h * 2 + 1];
                if (EPI == 1) {
                    float bias = sq[r];
                    float p0 = expf(v0 * PROJ_SCALE - bias) * RSQ_M;
                    float p1 = expf(v1 * PROJ_SCALE - bias) * RSQ_M;
                    unsigned hh, ll;
                    packpair(p0, p1, hh, ll);
                    long o = (long)r * (ldc / 2) + c0 / 2;
                    OH[o] = hh; OL[o] = ll;
                    if (OH2) {
                        int gg = (rowBlk >> 4) + wm * 4 + mi;
                        int ss = (colBlk >> 4) + wn * 4 + (ni >> 1);
                        long a = (((long)gg * SAout + ss) * 32 + gid * 4 + tig) * 4
                                 + (h + 2 * (ni & 1));
                        OH2[a] = hh; OL2[a] = ll;
                    }
                } else if (EPI == 2) {
                    long o = (long)r * ldc + c0;
                    atomicAdd(&Cb[o], v0);
                    atomicAdd(&Cb[o + 1], v1);
                } else {
                    float inv = 1.0f / den[b * Ln + r];
                    float fa0 = v0 * inv, fa1 = v1 * inv;
                    long go = (long)b * batchC + (long)r * ldc + c0;
                    C[go]     = content[go] + fa0;
                    C[go + 1] = content[go + 1] + fa1;
                    out2[go]     = fa0;
                    out2[go + 1] = fa1;
                }
            }
        }
    }
}

// ---------------------------------------------------------------------------
__global__ void den_kernel(const unsigned* __restrict__ ph, const unsigned* __restrict__ pl,
                           const float* __restrict__ Z, float* __restrict__ den)
{
    int row  = blockIdx.x * 8 + (threadIdx.x >> 5);
    int lane = threadIdx.x & 31;
    int b = row / Ln;
    uint4 h = ((const uint4*)(ph + (long)row * (Mf/2)))[lane];
    uint4 l = ((const uint4*)(pl + (long)row * (Mf/2)))[lane];
    const float* z = Z + b * Mf + lane * 8;
    unsigned hw[4] = {h.x, h.y, h.z, h.w};
    unsigned lw[4] = {l.x, l.y, l.z, l.w};
    float s = 0.f;
    #pragma unroll
    for (int j = 0; j < 4; j++) {
        s += (bfu((unsigned short)(hw[j] & 0xffff)) + bfu((unsigned short)(lw[j] & 0xffff))) * z[2*j];
        s += (bfu((unsigned short)(hw[j] >> 16))    + bfu((unsigned short)(lw[j] >> 16)))    * z[2*j+1];
    }
    #pragma unroll
    for (int o = 16; o; o >>= 1) s += __shfl_xor_sync(0xffffffffu, s, o);
    if (lane == 0) den[row] = s + 1e-8f;
}

// ---------------------------------------------------------------------------
#define SPLIT_S 4

extern "C" void kernel_launch(void* const* d_in, const int* in_sizes, int n_in,
                              void* d_out, int out_size)
{
    const float* content = (const float*)d_in[0];
    const float* style   = (const float*)d_in[1];
    const float* W       = (const float*)d_in[2];
    float* out = (float*)d_out;

    unsigned *cAh,*cAl,*sAh,*sAl,*wBh,*wBl,*spBh,*spBl,*pqh,*pql,*pqch,*pqcl,
             *pkh,*pkl,*pkTh,*pkTl,*sBh,*sBl;
    float *S, *Z, *den, *sqq, *sqk;
    cudaGetSymbolAddress((void**)&cAh, g_cA_h);   cudaGetSymbolAddress((void**)&cAl, g_cA_l);
    cudaGetSymbolAddress((void**)&sAh, g_sA_h);   cudaGetSymbolAddress((void**)&sAl, g_sA_l);
    cudaGetSymbolAddress((void**)&wBh, g_wB_h);   cudaGetSymbolAddress((void**)&wBl, g_wB_l);
    cudaGetSymbolAddress((void**)&spBh, g_spB_h); cudaGetSymbolAddress((void**)&spBl, g_spB_l);
    cudaGetSymbolAddress((void**)&pqh, g_pq_h);   cudaGetSymbolAddress((void**)&pql, g_pq_l);
    cudaGetSymbolAddress((void**)&pqch, g_pqc_h); cudaGetSymbolAddress((void**)&pqcl, g_pqc_l);
    cudaGetSymbolAddress((void**)&pkh, g_pk_h);   cudaGetSymbolAddress((void**)&pkl, g_pk_l);
    cudaGetSymbolAddress((void**)&pkTh, g_pkT_h); cudaGetSymbolAddress((void**)&pkTl, g_pkT_l);
    cudaGetSymbolAddress((void**)&sBh, g_sB_h);   cudaGetSymbolAddress((void**)&sBl, g_sB_l);
    cudaGetSymbolAddress((void**)&S,   g_S);
    cudaGetSymbolAddress((void**)&Z,   g_Z);
    cudaGetSymbolAddress((void**)&den, g_den);
    cudaGetSymbolAddress((void**)&sqq, g_sq_q);
    cudaGetSymbolAddress((void**)&sqk, g_sq_k);

    cudaFuncSetAttribute(tc_gemm<1>, cudaFuncAttributeMaxDynamicSharedMemorySize, SMEM_BYTES);
    cudaFuncSetAttribute(tc_gemm<2>, cudaFuncAttributeMaxDynamicSharedMemorySize, SMEM_BYTES);
    cudaFuncSetAttribute(tc_gemm<3>, cudaFuncAttributeMaxDynamicSharedMemorySize, SMEM_BYTES);

    // 1) zero S, Z (Z accumulated by transpack)
    zero_kernel<<<(Bn * Mf * Dn) / 256, 256>>>(S, Z);

    // 2) sum-of-squares + canonical-A packs
    rowsumsq_pack<<<ROWS_Q / 16, 256>>>(content, sqq, cAh, cAl);
    rowsumsq_pack<<<ROWS_K / 16, 256>>>(style, sqk, sAh, sAl);

    // 3) canonical-B packs: W (gather form), style (coalesced form)
    packB_canon<<<(32 * 32) / 8, 256>>>(W, wBh, wBl, Dn, Mf, 0, 0);
    styleB_pack<<<ROWS_K / 16, 256>>>(style, spBh, spBl);

    // 4) phi_q = phi(content @ W): std + canonical outputs
    tc_gemm<1><<<dim3(Mf/128, ROWS_Q/128, 1), 128, SMEM_BYTES>>>(
        cAh, cAl, wBh, wBl, nullptr, Dn, 32, Mf, Mf, 16,
        0, 0, 0, 1, sqq, pqh, pql, pqch, pqcl, nullptr, nullptr, nullptr);

    // 5) phi_k = phi(style @ W): std output only
    tc_gemm<1><<<dim3(Mf/128, ROWS_K/128, 1), 128, SMEM_BYTES>>>(
        sAh, sAl, wBh, wBl, nullptr, Dn, 32, Mf, Mf, 0,
        0, 0, 0, 1, sqk, pkh, pkl, nullptr, nullptr, nullptr, nullptr, nullptr);

    // 6) transpose-pack phi_k -> canonical A (SA=512 per batch) + fused Z
    transpack<<<dim3(KLn/64, Mf/64, Bn), 256>>>(pkh, pkl, pkTh, pkTl, Z);

    // 7) S[b][m][d] = sum_kl phi_k^T * style  (split-K atomics)
    tc_gemm<2><<<dim3(Dn/128, Mf/128, Bn * SPLIT_S), 128, SMEM_BYTES>>>(
        pkTh, pkTl, spBh, spBl, S, KLn/SPLIT_S, 512, Dn, Dn, 0,
        16L*512*128, (long)512*64*64, (long)Mf*Dn, SPLIT_S,
        nullptr, nullptr, nullptr, nullptr, nullptr, nullptr, nullptr, nullptr);

    // 8) canonical-B pack of S
    packB_canon<<<(Bn * 16 * 64) / 8, 256>>>(S, sBh, sBl, Mf, Dn,
                                             (long)Mf * Dn, (long)16 * 64 * 32);

    // 9) den
    den_kernel<<<ROWS_Q / 8, 256>>>(pqh, pql, Z, den);

    // 10) num GEMM fused final
    tc_gemm<3><<<dim3(Dn/128, Ln/128, Bn), 128, SMEM_BYTES>>>(
        pqch, pqcl, sBh, sBl, out, Mf, 16, Dn, Dn, 0,
        (long)(Ln/16)*16*128, (long)16*64*64, (long)Ln*Dn, 1,
        nullptr, nullptr, nullptr, nullptr, nullptr, den, content,
        out + (long)ROWS_Q * Dn);
}

// round 15
// speedup vs baseline: 1.0323x; 1.0323x over previous
#include <cuda_runtime.h>
#include <cuda_bf16.h>
#include <math.h>
#include <stdint.h>

// Problem constants (B=8, L=2048, D=512, K=4, m=256)
#define Bn 8
#define Ln 2048
#define Dn 512
#define Mf 256
#define KLn 8192
#define ROWS_Q 16384
#define ROWS_K 65536

// ===========================================================================
// Canonical fragment layouts (u32 = bf16 pair, low16 = even k):
//  A: element (row r, kpair kp):  g=r>>4, b=(r&15)>>3, gid=r&7,
//     s=kp>>3, tig=kp&3, hi=(kp>>2)&1, j=b+2*hi
//     u32 index = ((g*SA + s)*32 + gid*4 + tig)*4 + j          (SA = K/16)
//  B: element (kp, col n): s=kp>>3, tig=kp&3, j=(kp>>2)&1, h=n>>3, gid=n&7
//     u32 index = ((s*(N/8) + h)*32 + gid*4 + tig)*2 + j
// ===========================================================================

__device__ unsigned g_cA_h[(size_t)(ROWS_Q/16)*32*128];      // content A canon
__device__ unsigned g_cA_l[(size_t)(ROWS_Q/16)*32*128];
__device__ unsigned g_sA_h[(size_t)(ROWS_K/16)*32*128];      // style A canon
__device__ unsigned g_sA_l[(size_t)(ROWS_K/16)*32*128];
__device__ unsigned g_wB_h[(size_t)32*32*64];                // W B canon
__device__ unsigned g_wB_l[(size_t)32*32*64];
__device__ unsigned g_spB_h[(size_t)Bn*512*64*64];           // style B canon
__device__ unsigned g_spB_l[(size_t)Bn*512*64*64];
__device__ unsigned g_pq_h[(size_t)ROWS_Q*(Mf/2)];           // phi_q std
__device__ unsigned g_pq_l[(size_t)ROWS_Q*(Mf/2)];
__device__ unsigned g_pqc_h[(size_t)(ROWS_Q/16)*16*128];     // phi_q A canon
__device__ unsigned g_pqc_l[(size_t)(ROWS_Q/16)*16*128];
__device__ unsigned g_pk_h[(size_t)ROWS_K*(Mf/2)];           // phi_k std
__device__ unsigned g_pk_l[(size_t)ROWS_K*(Mf/2)];
__device__ unsigned g_pkT_h[(size_t)Bn*16*512*128];          // phi_k^T A canon
__device__ unsigned g_pkT_l[(size_t)Bn*16*512*128];
__device__ unsigned g_sB_h[(size_t)Bn*16*64*64];             // S B canon
__device__ unsigned g_sB_l[(size_t)Bn*16*64*64];
__device__ float g_S[(size_t)Bn*Mf*Dn];
__device__ float g_Z[Bn*Mf];
__device__ float g_den[ROWS_Q];
__device__ float g_sq_q[ROWS_Q];
__device__ float g_sq_k[ROWS_K];

__device__ __constant__ float PROJ_SCALE = 0.21022410381342864f;  // 512^-0.25
__device__ __constant__ float SQ_SCALE   = 0.022097086912079608f; // 1/(2*sqrt(512))
__device__ __constant__ float RSQ_M      = 0.0625f;               // 256^-0.5

// ---------------- helpers ----------------------------------------------------
__device__ __forceinline__ uint32_t smem_addr(const void* p) {
    uint32_t a;
    asm("{ .reg .u64 t; cvta.to.shared.u64 t, %1; cvt.u32.u64 %0, t; }" : "=r"(a) : "l"(p));
    return a;
}
__device__ __forceinline__ void split1(float x, unsigned short& h, unsigned short& l) {
    __nv_bfloat16 hb = __float2bfloat16_rn(x);
    h = __bfloat16_as_ushort(hb);
    l = __bfloat16_as_ushort(__float2bfloat16_rn(x - __bfloat162float(hb)));
}
__device__ __forceinline__ float bfu(unsigned short u) {
    return __bfloat162float(__ushort_as_bfloat16(u));
}
__device__ __forceinline__ void packpair(float a, float b, unsigned& h, unsigned& l) {
    unsigned short ha, la, hb, lb;
    split1(a, ha, la); split1(b, hb, lb);
    h = (unsigned)ha | ((unsigned)hb << 16);
    l = (unsigned)la | ((unsigned)lb << 16);
}
__device__ __forceinline__ void cp16(uint32_t d, const void* g) {
    asm volatile("cp.async.cg.shared.global [%0], [%1], 16;" :: "r"(d), "l"(g));
}
__device__ __forceinline__ void mma_bf16(float c[4], const unsigned a[4], const unsigned b[2]) {
    asm volatile(
        "mma.sync.aligned.m16n8k16.row.col.f32.bf16.bf16.f32 "
        "{%0,%1,%2,%3}, {%4,%5,%6,%7}, {%8,%9}, {%0,%1,%2,%3};\n"
        : "+f"(c[0]), "+f"(c[1]), "+f"(c[2]), "+f"(c[3])
        : "r"(a[0]), "r"(a[1]), "r"(a[2]), "r"(a[3]), "r"(b[0]), "r"(b[1]));
}

// ---------------------------------------------------------------------------
// rowsumsq + canonical-A pack.  grid = rows/16, block = 256.
// ---------------------------------------------------------------------------
__global__ void rowsumsq_pack(const float* __restrict__ X, float* __restrict__ sq,
                              unsigned* __restrict__ OH, unsigned* __restrict__ OL)
{
    int g = blockIdx.x;
    int w = threadIdx.x >> 5;
    int s = threadIdx.x & 31;
    int r0 = g * 16 + w;
    int r1 = r0 + 8;

    float f0[16], f1[16];
    {
        const float4* p0 = (const float4*)(X + (long)r0 * Dn + s * 16);
        const float4* p1 = (const float4*)(X + (long)r1 * Dn + s * 16);
        #pragma unroll
        for (int i = 0; i < 4; i++) {
            float4 v = p0[i];
            f0[4*i] = v.x; f0[4*i+1] = v.y; f0[4*i+2] = v.z; f0[4*i+3] = v.w;
            v = p1[i];
            f1[4*i] = v.x; f1[4*i+1] = v.y; f1[4*i+2] = v.z; f1[4*i+3] = v.w;
        }
    }
    float s0 = 0.f, s1 = 0.f;
    #pragma unroll
    for (int i = 0; i < 16; i++) { s0 += f0[i]*f0[i]; s1 += f1[i]*f1[i]; }
    #pragma unroll
    for (int o = 16; o; o >>= 1) {
        s0 += __shfl_xor_sync(0xffffffffu, s0, o);
        s1 += __shfl_xor_sync(0xffffffffu, s1, o);
    }
    if (s == 0) { sq[r0] = s0 * SQ_SCALE; sq[r1] = s1 * SQ_SCALE; }

    unsigned wh[16], wl[16];
    #pragma unroll
    for (int tig = 0; tig < 4; tig++) {
        #pragma unroll
        for (int q = 0; q < 4; q++) {
            int t = tig + 4 * (q >> 1);
            const float* f = (q & 1) ? f1 : f0;
            packpair(f[2*t], f[2*t+1], wh[tig*4+q], wl[tig*4+q]);
        }
    }
    long base = (((long)g * 32 + s) * 32 + w * 4) * 4;
    #pragma unroll
    for (int i = 0; i < 4; i++) {
        *(uint4*)(OH + base + i * 4) = make_uint4(wh[4*i], wh[4*i+1], wh[4*i+2], wh[4*i+3]);
        *(uint4*)(OL + base + i * 4) = make_uint4(wl[4*i], wl[4*i+1], wl[4*i+2], wl[4*i+3]);
    }
}

// ---------------------------------------------------------------------------
// styleB_pack: canonical-B pack of style with coalesced reads AND writes.
// ---------------------------------------------------------------------------
__global__ void styleB_pack(const float* __restrict__ X,
                            unsigned* __restrict__ BH, unsigned* __restrict__ BL)
{
    int g = blockIdx.x;
    const float* tb = X + (long)g * 16 * Dn;
    int bb = g >> 9;
    long sL = g & 511;
    #pragma unroll
    for (int rep = 0; rep < 2; rep++) {
        int n = threadIdx.x + rep * 256;
        int hB = n >> 3, gidn = n & 7;
        unsigned bh[8], bl[8];
        #pragma unroll
        for (int t = 0; t < 8; t++)
            packpair(tb[(long)(2*t) * Dn + n], tb[(long)(2*t+1) * Dn + n], bh[t], bl[t]);
        long o = (long)bb * (512L*64*64) + ((sL * 64 + hB) * 32 + gidn * 4) * 2;
        *(uint4*)(BH + o)     = make_uint4(bh[0], bh[4], bh[1], bh[5]);
        *(uint4*)(BH + o + 4) = make_uint4(bh[2], bh[6], bh[3], bh[7]);
        *(uint4*)(BL + o)     = make_uint4(bl[0], bl[4], bl[1], bl[5]);
        *(uint4*)(BL + o + 4) = make_uint4(bl[2], bl[6], bl[3], bl[7]);
    }
}

// ---------------------------------------------------------------------------
// Canonical-B pack from fp32 [K][N] (batched). Used for W and S.
// ---------------------------------------------------------------------------
__global__ void packB_canon(const float* __restrict__ src,
                            unsigned* __restrict__ dh, unsigned* __restrict__ dl,
                            int K, int N, long srcBatch, long dstBatchU2)
{
    long blk = (long)blockIdx.x * 8 + (threadIdx.x >> 5);
    int lane = threadIdx.x & 31;
    int gid = lane >> 2, tig = lane & 3;
    long perBatch = (long)(K / 16) * (N / 8);
    int bb = (int)(blk / perBatch);
    long rem = blk % perBatch;
    int s = (int)(rem / (N / 8));
    int h = (int)(rem % (N / 8));
    int n = h * 8 + gid;
    const float* sb = src + (long)bb * srcBatch;
    unsigned h0, l0, h1, l1;
    {
        int r = 16 * s + 2 * tig;
        packpair(sb[(long)r * N + n], sb[(long)(r + 1) * N + n], h0, l0);
        packpair(sb[(long)(r + 8) * N + n], sb[(long)(r + 9) * N + n], h1, l1);
    }
    long u2 = (long)bb * dstBatchU2 + ((long)s * (N / 8) + h) * 32 + lane;
    ((uint2*)dh)[u2] = make_uint2(h0, h1);
    ((uint2*)dl)[u2] = make_uint2(l0, l1);
}

// ---------------------------------------------------------------------------
// transpose-pack phi_k std -> canonical-A [b][m][kl] (SA=512), with fused Z.
// ---------------------------------------------------------------------------
__global__ void transpack(const unsigned* __restrict__ sh_, const unsigned* __restrict__ sl_,
                          unsigned* __restrict__ dh, unsigned* __restrict__ dl,
                          float* __restrict__ Z)
{
    __shared__ unsigned Th[64][33], Tl[64][33];
    int tk = blockIdx.x, tm = blockIdx.y, bb = blockIdx.z;
    const unsigned* sh = sh_ + ((long)bb * KLn + tk * 64) * (Mf/2) + tm * 32;
    const unsigned* sl = sl_ + ((long)bb * KLn + tk * 64) * (Mf/2) + tm * 32;
    int r = threadIdx.x >> 3, c4 = (threadIdx.x & 7) * 4;
    {
        uint4 v = *(const uint4*)(sh + (long)r * (Mf/2) + c4);
        Th[r][c4] = v.x; Th[r][c4+1] = v.y; Th[r][c4+2] = v.z; Th[r][c4+3] = v.w;
        v = *(const uint4*)(sh + (long)(r + 32) * (Mf/2) + c4);
        Th[r+32][c4] = v.x; Th[r+32][c4+1] = v.y; Th[r+32][c4+2] = v.z; Th[r+32][c4+3] = v.w;
        v = *(const uint4*)(sl + (long)r * (Mf/2) + c4);
        Tl[r][c4] = v.x; Tl[r][c4+1] = v.y; Tl[r][c4+2] = v.z; Tl[r][c4+3] = v.w;
        v = *(const uint4*)(sl + (long)(r + 32) * (Mf/2) + c4);
        Tl[r+32][c4] = v.x; Tl[r+32][c4+1] = v.y; Tl[r+32][c4+2] = v.z; Tl[r+32][c4+3] = v.w;
    }
    __syncthreads();
    int m = threadIdx.x >> 2;
    int kj = (threadIdx.x & 3) * 8;
    int mp = m >> 1, pm = m & 1;
    unsigned oh[8], ol[8];
    float zsum = 0.f;
    #pragma unroll
    for (int j = 0; j < 8; j++) {
        int klp = kj + j;
        unsigned t0 = Th[2*klp][mp],   t1 = Th[2*klp+1][mp];
        unsigned u0 = Tl[2*klp][mp],   u1 = Tl[2*klp+1][mp];
        unsigned e0 = pm ? (t0 >> 16) : (t0 & 0xffff);
        unsigned e1 = pm ? (t1 >> 16) : (t1 & 0xffff);
        oh[j] = e0 | (e1 << 16);
        unsigned f0 = pm ? (u0 >> 16) : (u0 & 0xffff);
        unsigned f1 = pm ? (u1 >> 16) : (u1 & 0xffff);
        ol[j] = f0 | (f1 << 16);
        zsum += bfu((unsigned short)e0) + bfu((unsigned short)e1)
              + bfu((unsigned short)f0) + bfu((unsigned short)f1);
    }
    int mg = tm * 64 + m;
    atomicAdd(&Z[bb * Mf + mg], zsum);
    int g = mg >> 4, b_ = (mg & 15) >> 3, gidw = mg & 7;
    int sS = (tk * 32 + kj) >> 3;
    long base = (long)bb * (16L * 512 * 128) + (((long)g * 512 + sS) * 32 + gidw * 4) * 4;
    #pragma unroll
    for (int j = 0; j < 8; j++) {
        int tig = j & 3, hi = j >> 2;
        long a = base + tig * 4 + b_ + 2 * hi;
        dh[a] = oh[j]; dl[a] = ol[j];
    }
}

__global__ void zero_kernel(float* __restrict__ S, float* __restrict__ Z)
{
    long i = (long)blockIdx.x * 256 + threadIdx.x;
    if (i < (long)Bn * Mf * Dn) S[i] = 0.f;
    if (i < Bn * Mf)            Z[i] = 0.f;
}

// ---------------------------------------------------------------------------
// Canonical-layout bf16x2-compensated GEMM (round-12 proven core),
// 3-stage cp.async pipeline, forced 2 CTAs/SM via launch_bounds.
//  Stage (u32): AH 0..2047 | AL 2048..4095 | BH 4096..5119 | BL 5120..6143
// ---------------------------------------------------------------------------
#define STG_U32 6144
#define N_STAGES 3
#define SMEM_BYTES (N_STAGES * STG_U32 * 4)

template<int EPI>
__global__ void __launch_bounds__(256, 2)
tc_gemm(const unsigned* __restrict__ Ah, const unsigned* __restrict__ Al,
        const unsigned* __restrict__ Bh, const unsigned* __restrict__ Bl,
        float* __restrict__ C, int Ksz, int SA, int Nt, int ldc, int SAout,
        long batchA, long batchB, long batchC, int splitK,
        const float* __restrict__ sq,
        unsigned* __restrict__ OH, unsigned* __restrict__ OL,
        unsigned* __restrict__ OH2, unsigned* __restrict__ OL2,
        const float* __restrict__ den, const float* __restrict__ content,
        float* __restrict__ out2)
{
    extern __shared__ __align__(16) unsigned sm[];

    int bz = blockIdx.z;
    int b  = bz / splitK;
    int sp = bz % splitK;
    int sBeg = sp * (Ksz / 16);

    const unsigned* Agh = Ah + (long)b * batchA;
    const unsigned* Agl = Al + (long)b * batchA;
    const unsigned* Bgh = Bh + (long)b * batchB;
    const unsigned* Bgl = Bl + (long)b * batchB;

    int rowBlk = blockIdx.y * 128;
    int colBlk = blockIdx.x * 64;
    int gA = rowBlk >> 4;
    int hA = colBlk >> 3;
    int tid = threadIdx.x, wid = tid >> 5, lane = tid & 31;
    int gid = lane >> 2, tig = lane & 3;
    int wm = wid >> 1, wn = wid & 1;

    auto loadStage = [&](int t, int st) {
        unsigned* base = sm + st * STG_U32;
        int s0 = sBeg + 2 * t;
        {
            int blk = tid >> 4;
            int gl = blk >> 1, sl = blk & 1;
            long src = (((long)(gA + gl)) * SA + (s0 + sl)) * 128 + (tid & 15) * 8;
            uint32_t dst = smem_addr(base + blk * 128 + (tid & 15) * 8);
            cp16(dst,      Agh + src);
            cp16(dst + 16, Agh + src + 4);
            cp16(dst + 8192,      Agl + src);
            cp16(dst + 8192 + 16, Agl + src + 4);
        }
        {
            int blk = tid >> 4;
            int sl = blk >> 3, hl = blk & 7;
            long src = ((long)(s0 + sl)) * (Nt / 8) * 64 + (long)(hA + hl) * 64 + (tid & 15) * 4;
            uint32_t dst = smem_addr(base + 4096 + blk * 64 + (tid & 15) * 4);
            cp16(dst, Bgh + src);
            cp16(dst + 4096, Bgl + src);
        }
    };

    float acc[2][4][4] = {};
    int nT = Ksz / 32;

    loadStage(0, 0);
    asm volatile("cp.async.commit_group;" ::: "memory");
    loadStage(1, 1);
    asm volatile("cp.async.commit_group;" ::: "memory");

    for (int t = 0; t < nT; t++) {
        asm volatile("cp.async.wait_group 1;" ::: "memory");
        __syncthreads();

        if (t + 2 < nT) {
            loadStage(t + 2, (t + 2) % N_STAGES);
            asm volatile("cp.async.commit_group;" ::: "memory");
        } else {
            asm volatile("cp.async.commit_group;" ::: "memory");
        }

        unsigned* base = sm + (t % N_STAGES) * STG_U32;

        #pragma unroll
        for (int kk = 0; kk < 2; kk++) {
            unsigned afh[2][4], afl[2][4], bfh[4][2], bfl[4][2];
            #pragma unroll
            for (int mi = 0; mi < 2; mi++) {
                int off = ((wm * 2 + mi) * 2 + kk) * 128 + lane * 4;
                uint4 v = *(uint4*)(base + off);
                afh[mi][0] = v.x; afh[mi][1] = v.y; afh[mi][2] = v.z; afh[mi][3] = v.w;
                v = *(uint4*)(base + 2048 + off);
                afl[mi][0] = v.x; afl[mi][1] = v.y; afl[mi][2] = v.z; afl[mi][3] = v.w;
            }
            #pragma unroll
            for (int ni = 0; ni < 4; ni++) {
                int off = 4096 + (kk * 8 + wn * 4 + ni) * 64 + lane * 2;
                uint2 v = *(uint2*)(base + off);
                bfh[ni][0] = v.x; bfh[ni][1] = v.y;
                v = *(uint2*)(base + 1024 + off);
                bfl[ni][0] = v.x; bfl[ni][1] = v.y;
            }
            #pragma unroll
            for (int mi = 0; mi < 2; mi++)
                #pragma unroll
                for (int ni = 0; ni < 4; ni++) {
                    mma_bf16(acc[mi][ni], afl[mi], bfh[ni]);
                    mma_bf16(acc[mi][ni], afh[mi], bfl[ni]);
                    mma_bf16(acc[mi][ni], afh[mi], bfh[ni]);
                }
        }
    }
    asm volatile("cp.async.wait_group 0;" ::: "memory");

    // ---- epilogue ----
    float* Cb = C + (long)b * batchC;
    #pragma unroll
    for (int mi = 0; mi < 2; mi++) {
        #pragma unroll
        for (int ni = 0; ni < 4; ni++) {
            int r0 = rowBlk + wm * 32 + mi * 16 + gid;
            int c0 = colBlk + wn * 32 + ni * 8 + tig * 2;
            #pragma unroll
            for (int h = 0; h < 2; h++) {
                int r = r0 + h * 8;
                float v0 = acc[mi][ni][h * 2 + 0];
                float v1 = acc[mi][ni][h * 2 + 1];
                if (EPI == 1) {
                    float bias = sq[r];
                    float p0 = expf(v0 * PROJ_SCALE - bias) * RSQ_M;
                    float p1 = expf(v1 * PROJ_SCALE - bias) * RSQ_M;
                    unsigned hh, ll;
                    packpair(p0, p1, hh, ll);
                    long o = (long)r * (ldc / 2) + c0 / 2;
                    OH[o] = hh; OL[o] = ll;
                    if (OH2) {
                        int gg = (rowBlk >> 4) + wm * 2 + mi;
                        int ss = (colBlk >> 4) + wn * 2 + (ni >> 1);
                        long a = (((long)gg * SAout + ss) * 32 + gid * 4 + tig) * 4
                                 + (h + 2 * (ni & 1));
                        OH2[a] = hh; OL2[a] = ll;
                    }
                } else if (EPI == 2) {
                    long o = (long)r * ldc + c0;
                    atomicAdd(&Cb[o], v0);
                    atomicAdd(&Cb[o + 1], v1);
                } else {
                    float inv = 1.0f / den[b * Ln + r];
                    float fa0 = v0 * inv, fa1 = v1 * inv;
                    long go = (long)b * batchC + (long)r * ldc + c0;
                    C[go]     = content[go] + fa0;
                    C[go + 1] = content[go + 1] + fa1;
                    out2[go]     = fa0;
                    out2[go + 1] = fa1;
                }
            }
        }
    }
}

// ---------------------------------------------------------------------------
__global__ void den_kernel(const unsigned* __restrict__ ph, const unsigned* __restrict__ pl,
                           const float* __restrict__ Z, float* __restrict__ den)
{
    int row  = blockIdx.x * 8 + (threadIdx.x >> 5);
    int lane = threadIdx.x & 31;
    int b = row / Ln;
    uint4 h = ((const uint4*)(ph + (long)row * (Mf/2)))[lane];
    uint4 l = ((const uint4*)(pl + (long)row * (Mf/2)))[lane];
    const float* z = Z + b * Mf + lane * 8;
    unsigned hw[4] = {h.x, h.y, h.z, h.w};
    unsigned lw[4] = {l.x, l.y, l.z, l.w};
    float s = 0.f;
    #pragma unroll
    for (int j = 0; j < 4; j++) {
        s += (bfu((unsigned short)(hw[j] & 0xffff)) + bfu((unsigned short)(lw[j] & 0xffff))) * z[2*j];
        s += (bfu((unsigned short)(hw[j] >> 16))    + bfu((unsigned short)(lw[j] >> 16)))    * z[2*j+1];
    }
    #pragma unroll
    for (int o = 16; o; o >>= 1) s += __shfl_xor_sync(0xffffffffu, s, o);
    if (lane == 0) den[row] = s + 1e-8f;
}

// ---------------------------------------------------------------------------
#define SPLIT_S 4

extern "C" void kernel_launch(void* const* d_in, const int* in_sizes, int n_in,
                              void* d_out, int out_size)
{
    const float* content = (const float*)d_in[0];
    const float* style   = (const float*)d_in[1];
    const float* W       = (const float*)d_in[2];
    float* out = (float*)d_out;

    unsigned *cAh,*cAl,*sAh,*sAl,*wBh,*wBl,*spBh,*spBl,*pqh,*pql,*pqch,*pqcl,
             *pkh,*pkl,*pkTh,*pkTl,*sBh,*sBl;
    float *S, *Z, *den, *sqq, *sqk;
    cudaGetSymbolAddress((void**)&cAh, g_cA_h);   cudaGetSymbolAddress((void**)&cAl, g_cA_l);
    cudaGetSymbolAddress((void**)&sAh, g_sA_h);   cudaGetSymbolAddress((void**)&sAl, g_sA_l);
    cudaGetSymbolAddress((void**)&wBh, g_wB_h);   cudaGetSymbolAddress((void**)&wBl, g_wB_l);
    cudaGetSymbolAddress((void**)&spBh, g_spB_h); cudaGetSymbolAddress((void**)&spBl, g_spB_l);
    cudaGetSymbolAddress((void**)&pqh, g_pq_h);   cudaGetSymbolAddress((void**)&pql, g_pq_l);
    cudaGetSymbolAddress((void**)&pqch, g_pqc_h); cudaGetSymbolAddress((void**)&pqcl, g_pqc_l);
    cudaGetSymbolAddress((void**)&pkh, g_pk_h);   cudaGetSymbolAddress((void**)&pkl, g_pk_l);
    cudaGetSymbolAddress((void**)&pkTh, g_pkT_h); cudaGetSymbolAddress((void**)&pkTl, g_pkT_l);
    cudaGetSymbolAddress((void**)&sBh, g_sB_h);   cudaGetSymbolAddress((void**)&sBl, g_sB_l);
    cudaGetSymbolAddress((void**)&S,   g_S);
    cudaGetSymbolAddress((void**)&Z,   g_Z);
    cudaGetSymbolAddress((void**)&den, g_den);
    cudaGetSymbolAddress((void**)&sqq, g_sq_q);
    cudaGetSymbolAddress((void**)&sqk, g_sq_k);

    cudaFuncSetAttribute(tc_gemm<1>, cudaFuncAttributeMaxDynamicSharedMemorySize, SMEM_BYTES);
    cudaFuncSetAttribute(tc_gemm<2>, cudaFuncAttributeMaxDynamicSharedMemorySize, SMEM_BYTES);
    cudaFuncSetAttribute(tc_gemm<3>, cudaFuncAttributeMaxDynamicSharedMemorySize, SMEM_BYTES);

    // Launch order arranged so the ncu capture slot (index 3) lands on the
    // phi_k GEMM (largest launch) for direct GEMM visibility.

    // 0) style sum-of-squares + canonical-A pack
    rowsumsq_pack<<<ROWS_K / 16, 256>>>(style, sqk, sAh, sAl);
    // 1) canonical-B pack: W
    packB_canon<<<(32 * 32) / 8, 256>>>(W, wBh, wBl, Dn, Mf, 0, 0);
    // 2) zero S, Z (Z accumulated by transpack)
    zero_kernel<<<(Bn * Mf * Dn) / 256, 256>>>(S, Z);
    // 3) phi_k = phi(style @ W): std output only   <-- ncu capture slot
    tc_gemm<1><<<dim3(Mf/64, ROWS_K/128, 1), 256, SMEM_BYTES>>>(
        sAh, sAl, wBh, wBl, nullptr, Dn, 32, Mf, Mf, 0,
        0, 0, 0, 1, sqk, pkh, pkl, nullptr, nullptr, nullptr, nullptr, nullptr);
    // 4) content sum-of-squares + canonical-A pack
    rowsumsq_pack<<<ROWS_Q / 16, 256>>>(content, sqq, cAh, cAl);
    // 5) canonical-B pack: style (coalesced form)
    styleB_pack<<<ROWS_K / 16, 256>>>(style, spBh, spBl);
    // 6) phi_q = phi(content @ W): std + canonical outputs
    tc_gemm<1><<<dim3(Mf/64, ROWS_Q/128, 1), 256, SMEM_BYTES>>>(
        cAh, cAl, wBh, wBl, nullptr, Dn, 32, Mf, Mf, 16,
        0, 0, 0, 1, sqq, pqh, pql, pqch, pqcl, nullptr, nullptr, nullptr);
    // 7) transpose-pack phi_k -> canonical A (SA=512 per batch) + fused Z
    transpack<<<dim3(KLn/64, Mf/64, Bn), 256>>>(pkh, pkl, pkTh, pkTl, Z);
    // 8) S[b][m][d] = sum_kl phi_k^T * style  (split-K atomics)
    tc_gemm<2><<<dim3(Dn/64, Mf/128, Bn * SPLIT_S), 256, SMEM_BYTES>>>(
        pkTh, pkTl, spBh, spBl, S, KLn/SPLIT_S, 512, Dn, Dn, 0,
        16L*512*128, (long)512*64*64, (long)Mf*Dn, SPLIT_S,
        nullptr, nullptr, nullptr, nullptr, nullptr, nullptr, nullptr, nullptr);
    // 9) canonical-B pack of S
    packB_canon<<<(Bn * 16 * 64) / 8, 256>>>(S, sBh, sBl, Mf, Dn,
                                             (long)Mf * Dn, (long)16 * 64 * 32);
    // 10) den
    den_kernel<<<ROWS_Q / 8, 256>>>(pqh, pql, Z, den);
    // 11) num GEMM fused final
    tc_gemm<3><<<dim3(Dn/64, Ln/128, Bn), 256, SMEM_BYTES>>>(
        pqch, pqcl, sBh, sBl, out, Mf, 16, Dn, Dn, 0,
        (long)(Ln/16)*16*128, (long)16*64*64, (long)Ln*Dn, 1,
        nullptr, nullptr, nullptr, nullptr, nullptr, den, content,
        out + (long)ROWS_Q * Dn);
}

// round 16
// speedup vs baseline: 1.0483x; 1.0155x over previous
#include <cuda_runtime.h>
#include <cuda_bf16.h>
#include <math.h>
#include <stdint.h>

// Problem constants (B=8, L=2048, D=512, K=4, m=256)
#define Bn 8
#define Ln 2048
#define Dn 512
#define Mf 256
#define KLn 8192
#define ROWS_Q 16384
#define ROWS_K 65536

// ===========================================================================
// Canonical fragment layouts (u32 = bf16 pair, low16 = even k):
//  A: element (row r, kpair kp):  g=r>>4, b=(r&15)>>3, gid=r&7,
//     s=kp>>3, tig=kp&3, hi=(kp>>2)&1, j=b+2*hi
//     u32 index = ((g*SA + s)*32 + gid*4 + tig)*4 + j          (SA = K/16)
//  B: element (kp, col n): s=kp>>3, tig=kp&3, j=(kp>>2)&1, h=n>>3, gid=n&7
//     u32 index = ((s*(N/8) + h)*32 + gid*4 + tig)*2 + j
// ===========================================================================

__device__ unsigned g_cA_h[(size_t)(ROWS_Q/16)*32*128];      // content A canon
__device__ unsigned g_cA_l[(size_t)(ROWS_Q/16)*32*128];
__device__ unsigned g_sA_h[(size_t)(ROWS_K/16)*32*128];      // style A canon
__device__ unsigned g_sA_l[(size_t)(ROWS_K/16)*32*128];
__device__ unsigned g_wB_h[(size_t)32*32*64];                // W B canon
__device__ unsigned g_wB_l[(size_t)32*32*64];
__device__ unsigned g_spB_h[(size_t)Bn*512*64*64];           // style B canon
__device__ unsigned g_spB_l[(size_t)Bn*512*64*64];
__device__ unsigned g_pq_h[(size_t)ROWS_Q*(Mf/2)];           // phi_q std
__device__ unsigned g_pq_l[(size_t)ROWS_Q*(Mf/2)];
__device__ unsigned g_pqc_h[(size_t)(ROWS_Q/16)*16*128];     // phi_q A canon
__device__ unsigned g_pqc_l[(size_t)(ROWS_Q/16)*16*128];
__device__ unsigned g_pk_h[(size_t)ROWS_K*(Mf/2)];           // phi_k std
__device__ unsigned g_pk_l[(size_t)ROWS_K*(Mf/2)];
__device__ unsigned g_pkT_h[(size_t)Bn*16*512*128];          // phi_k^T A canon
__device__ unsigned g_pkT_l[(size_t)Bn*16*512*128];
__device__ unsigned g_sB_h[(size_t)Bn*16*64*64];             // S B canon
__device__ unsigned g_sB_l[(size_t)Bn*16*64*64];
__device__ float g_S[(size_t)Bn*Mf*Dn];
__device__ float g_Z[Bn*Mf];
__device__ float g_den[ROWS_Q];
__device__ float g_sq_q[ROWS_Q];
__device__ float g_sq_k[ROWS_K];

__device__ __constant__ float PROJ_SCALE = 0.21022410381342864f;  // 512^-0.25
__device__ __constant__ float SQ_SCALE   = 0.022097086912079608f; // 1/(2*sqrt(512))
__device__ __constant__ float RSQ_M      = 0.0625f;               // 256^-0.5

// ---------------- helpers ----------------------------------------------------
__device__ __forceinline__ uint32_t smem_addr(const void* p) {
    uint32_t a;
    asm("{ .reg .u64 t; cvta.to.shared.u64 t, %1; cvt.u32.u64 %0, t; }" : "=r"(a) : "l"(p));
    return a;
}
__device__ __forceinline__ void split1(float x, unsigned short& h, unsigned short& l) {
    __nv_bfloat16 hb = __float2bfloat16_rn(x);
    h = __bfloat16_as_ushort(hb);
    l = __bfloat16_as_ushort(__float2bfloat16_rn(x - __bfloat162float(hb)));
}
__device__ __forceinline__ float bfu(unsigned short u) {
    return __bfloat162float(__ushort_as_bfloat16(u));
}
__device__ __forceinline__ void packpair(float a, float b, unsigned& h, unsigned& l) {
    unsigned short ha, la, hb, lb;
    split1(a, ha, la); split1(b, hb, lb);
    h = (unsigned)ha | ((unsigned)hb << 16);
    l = (unsigned)la | ((unsigned)lb << 16);
}
__device__ __forceinline__ void cp16(uint32_t d, const void* g) {
    asm volatile("cp.async.cg.shared.global [%0], [%1], 16;" :: "r"(d), "l"(g));
}
__device__ __forceinline__ void mma_bf16(float c[4], const unsigned a[4], const unsigned b[2]) {
    asm volatile(
        "mma.sync.aligned.m16n8k16.row.col.f32.bf16.bf16.f32 "
        "{%0,%1,%2,%3}, {%4,%5,%6,%7}, {%8,%9}, {%0,%1,%2,%3};\n"
        : "+f"(c[0]), "+f"(c[1]), "+f"(c[2]), "+f"(c[3])
        : "r"(a[0]), "r"(a[1]), "r"(a[2]), "r"(a[3]), "r"(b[0]), "r"(b[1]));
}

// ---------------------------------------------------------------------------
// rowsumsq + canonical-A pack.  grid = rows/16, block = 256.
// ---------------------------------------------------------------------------
__global__ void rowsumsq_pack(const float* __restrict__ X, float* __restrict__ sq,
                              unsigned* __restrict__ OH, unsigned* __restrict__ OL)
{
    int g = blockIdx.x;
    int w = threadIdx.x >> 5;
    int s = threadIdx.x & 31;
    int r0 = g * 16 + w;
    int r1 = r0 + 8;

    float f0[16], f1[16];
    {
        const float4* p0 = (const float4*)(X + (long)r0 * Dn + s * 16);
        const float4* p1 = (const float4*)(X + (long)r1 * Dn + s * 16);
        #pragma unroll
        for (int i = 0; i < 4; i++) {
            float4 v = p0[i];
            f0[4*i] = v.x; f0[4*i+1] = v.y; f0[4*i+2] = v.z; f0[4*i+3] = v.w;
            v = p1[i];
            f1[4*i] = v.x; f1[4*i+1] = v.y; f1[4*i+2] = v.z; f1[4*i+3] = v.w;
        }
    }
    float s0 = 0.f, s1 = 0.f;
    #pragma unroll
    for (int i = 0; i < 16; i++) { s0 += f0[i]*f0[i]; s1 += f1[i]*f1[i]; }
    #pragma unroll
    for (int o = 16; o; o >>= 1) {
        s0 += __shfl_xor_sync(0xffffffffu, s0, o);
        s1 += __shfl_xor_sync(0xffffffffu, s1, o);
    }
    if (s == 0) { sq[r0] = s0 * SQ_SCALE; sq[r1] = s1 * SQ_SCALE; }

    unsigned wh[16], wl[16];
    #pragma unroll
    for (int tig = 0; tig < 4; tig++) {
        #pragma unroll
        for (int q = 0; q < 4; q++) {
            int t = tig + 4 * (q >> 1);
            const float* f = (q & 1) ? f1 : f0;
            packpair(f[2*t], f[2*t+1], wh[tig*4+q], wl[tig*4+q]);
        }
    }
    long base = (((long)g * 32 + s) * 32 + w * 4) * 4;
    #pragma unroll
    for (int i = 0; i < 4; i++) {
        *(uint4*)(OH + base + i * 4) = make_uint4(wh[4*i], wh[4*i+1], wh[4*i+2], wh[4*i+3]);
        *(uint4*)(OL + base + i * 4) = make_uint4(wl[4*i], wl[4*i+1], wl[4*i+2], wl[4*i+3]);
    }
}

// ---------------------------------------------------------------------------
// styleB_pack: canonical-B pack of style with coalesced reads AND writes.
// ---------------------------------------------------------------------------
__global__ void styleB_pack(const float* __restrict__ X,
                            unsigned* __restrict__ BH, unsigned* __restrict__ BL)
{
    int g = blockIdx.x;
    const float* tb = X + (long)g * 16 * Dn;
    int bb = g >> 9;
    long sL = g & 511;
    #pragma unroll
    for (int rep = 0; rep < 2; rep++) {
        int n = threadIdx.x + rep * 256;
        int hB = n >> 3, gidn = n & 7;
        unsigned bh[8], bl[8];
        #pragma unroll
        for (int t = 0; t < 8; t++)
            packpair(tb[(long)(2*t) * Dn + n], tb[(long)(2*t+1) * Dn + n], bh[t], bl[t]);
        long o = (long)bb * (512L*64*64) + ((sL * 64 + hB) * 32 + gidn * 4) * 2;
        *(uint4*)(BH + o)     = make_uint4(bh[0], bh[4], bh[1], bh[5]);
        *(uint4*)(BH + o + 4) = make_uint4(bh[2], bh[6], bh[3], bh[7]);
        *(uint4*)(BL + o)     = make_uint4(bl[0], bl[4], bl[1], bl[5]);
        *(uint4*)(BL + o + 4) = make_uint4(bl[2], bl[6], bl[3], bl[7]);
    }
}

// ---------------------------------------------------------------------------
// Canonical-B pack from fp32 [K][N] (batched). Used for W and S.
// ---------------------------------------------------------------------------
__global__ void packB_canon(const float* __restrict__ src,
                            unsigned* __restrict__ dh, unsigned* __restrict__ dl,
                            int K, int N, long srcBatch, long dstBatchU2)
{
    long blk = (long)blockIdx.x * 8 + (threadIdx.x >> 5);
    int lane = threadIdx.x & 31;
    int gid = lane >> 2, tig = lane & 3;
    long perBatch = (long)(K / 16) * (N / 8);
    int bb = (int)(blk / perBatch);
    long rem = blk % perBatch;
    int s = (int)(rem / (N / 8));
    int h = (int)(rem % (N / 8));
    int n = h * 8 + gid;
    const float* sb = src + (long)bb * srcBatch;
    unsigned h0, l0, h1, l1;
    {
        int r = 16 * s + 2 * tig;
        packpair(sb[(long)r * N + n], sb[(long)(r + 1) * N + n], h0, l0);
        packpair(sb[(long)(r + 8) * N + n], sb[(long)(r + 9) * N + n], h1, l1);
    }
    long u2 = (long)bb * dstBatchU2 + ((long)s * (N / 8) + h) * 32 + lane;
    ((uint2*)dh)[u2] = make_uint2(h0, h1);
    ((uint2*)dl)[u2] = make_uint2(l0, l1);
}

// ---------------------------------------------------------------------------
// transpose-pack phi_k std -> canonical-A [b][m][kl] (SA=512), with fused Z.
// ---------------------------------------------------------------------------
__global__ void transpack(const unsigned* __restrict__ sh_, const unsigned* __restrict__ sl_,
                          unsigned* __restrict__ dh, unsigned* __restrict__ dl,
                          float* __restrict__ Z)
{
    __shared__ unsigned Th[64][33], Tl[64][33];
    int tk = blockIdx.x, tm = blockIdx.y, bb = blockIdx.z;
    const unsigned* sh = sh_ + ((long)bb * KLn + tk * 64) * (Mf/2) + tm * 32;
    const unsigned* sl = sl_ + ((long)bb * KLn + tk * 64) * (Mf/2) + tm * 32;
    int r = threadIdx.x >> 3, c4 = (threadIdx.x & 7) * 4;
    {
        uint4 v = *(const uint4*)(sh + (long)r * (Mf/2) + c4);
        Th[r][c4] = v.x; Th[r][c4+1] = v.y; Th[r][c4+2] = v.z; Th[r][c4+3] = v.w;
        v = *(const uint4*)(sh + (long)(r + 32) * (Mf/2) + c4);
        Th[r+32][c4] = v.x; Th[r+32][c4+1] = v.y; Th[r+32][c4+2] = v.z; Th[r+32][c4+3] = v.w;
        v = *(const uint4*)(sl + (long)r * (Mf/2) + c4);
        Tl[r][c4] = v.x; Tl[r][c4+1] = v.y; Tl[r][c4+2] = v.z; Tl[r][c4+3] = v.w;
        v = *(const uint4*)(sl + (long)(r + 32) * (Mf/2) + c4);
        Tl[r+32][c4] = v.x; Tl[r+32][c4+1] = v.y; Tl[r+32][c4+2] = v.z; Tl[r+32][c4+3] = v.w;
    }
    __syncthreads();
    int m = threadIdx.x >> 2;
    int kj = (threadIdx.x & 3) * 8;
    int mp = m >> 1, pm = m & 1;
    unsigned oh[8], ol[8];
    float zsum = 0.f;
    #pragma unroll
    for (int j = 0; j < 8; j++) {
        int klp = kj + j;
        unsigned t0 = Th[2*klp][mp],   t1 = Th[2*klp+1][mp];
        unsigned u0 = Tl[2*klp][mp],   u1 = Tl[2*klp+1][mp];
        unsigned e0 = pm ? (t0 >> 16) : (t0 & 0xffff);
        unsigned e1 = pm ? (t1 >> 16) : (t1 & 0xffff);
        oh[j] = e0 | (e1 << 16);
        unsigned f0 = pm ? (u0 >> 16) : (u0 & 0xffff);
        unsigned f1 = pm ? (u1 >> 16) : (u1 & 0xffff);
        ol[j] = f0 | (f1 << 16);
        zsum += bfu((unsigned short)e0) + bfu((unsigned short)e1)
              + bfu((unsigned short)f0) + bfu((unsigned short)f1);
    }
    int mg = tm * 64 + m;
    atomicAdd(&Z[bb * Mf + mg], zsum);
    int g = mg >> 4, b_ = (mg & 15) >> 3, gidw = mg & 7;
    int sS = (tk * 32 + kj) >> 3;
    long base = (long)bb * (16L * 512 * 128) + (((long)g * 512 + sS) * 32 + gidw * 4) * 4;
    #pragma unroll
    for (int j = 0; j < 8; j++) {
        int tig = j & 3, hi = j >> 2;
        long a = base + tig * 4 + b_ + 2 * hi;
        dh[a] = oh[j]; dl[a] = ol[j];
    }
}

__global__ void zero_kernel(float* __restrict__ S, float* __restrict__ Z)
{
    long i = (long)blockIdx.x * 256 + threadIdx.x;
    if (i < (long)Bn * Mf * Dn) S[i] = 0.f;
    if (i < Bn * Mf)            Z[i] = 0.f;
}

// ---------------------------------------------------------------------------
// Canonical-layout bf16x2-compensated GEMM body (round-12 proven core),
// 3-stage cp.async pipeline.
//  Stage (u32): AH 0..2047 | AL 2048..4095 | BH 4096..5119 | BL 5120..6143
// ---------------------------------------------------------------------------
#define STG_U32 6144
#define N_STAGES 3
#define SMEM_BYTES (N_STAGES * STG_U32 * 4)

template<int EPI>
__device__ __forceinline__ void
gemm_body(const unsigned* __restrict__ Ah, const unsigned* __restrict__ Al,
          const unsigned* __restrict__ Bh, const unsigned* __restrict__ Bl,
          float* __restrict__ C, int Ksz, int SA, int Nt, int ldc, int SAout,
          long batchA, long batchB, long batchC, int splitK,
          const float* __restrict__ sq,
          unsigned* __restrict__ OH, unsigned* __restrict__ OL,
          unsigned* __restrict__ OH2, unsigned* __restrict__ OL2,
          const float* __restrict__ den, const float* __restrict__ content,
          float* __restrict__ out2, unsigned* sm)
{
    int bz = blockIdx.z;
    int b  = bz / splitK;
    int sp = bz % splitK;
    int sBeg = sp * (Ksz / 16);

    const unsigned* Agh = Ah + (long)b * batchA;
    const unsigned* Agl = Al + (long)b * batchA;
    const unsigned* Bgh = Bh + (long)b * batchB;
    const unsigned* Bgl = Bl + (long)b * batchB;

    int rowBlk = blockIdx.y * 128;
    int colBlk = blockIdx.x * 64;
    int gA = rowBlk >> 4;
    int hA = colBlk >> 3;
    int tid = threadIdx.x, wid = tid >> 5, lane = tid & 31;
    int gid = lane >> 2, tig = lane & 3;
    int wm = wid >> 1, wn = wid & 1;

    auto loadStage = [&](int t, int st) {
        unsigned* base = sm + st * STG_U32;
        int s0 = sBeg + 2 * t;
        {
            int blk = tid >> 4;
            int gl = blk >> 1, sl = blk & 1;
            long src = (((long)(gA + gl)) * SA + (s0 + sl)) * 128 + (tid & 15) * 8;
            uint32_t dst = smem_addr(base + blk * 128 + (tid & 15) * 8);
            cp16(dst,      Agh + src);
            cp16(dst + 16, Agh + src + 4);
            cp16(dst + 8192,      Agl + src);
            cp16(dst + 8192 + 16, Agl + src + 4);
        }
        {
            int blk = tid >> 4;
            int sl = blk >> 3, hl = blk & 7;
            long src = ((long)(s0 + sl)) * (Nt / 8) * 64 + (long)(hA + hl) * 64 + (tid & 15) * 4;
            uint32_t dst = smem_addr(base + 4096 + blk * 64 + (tid & 15) * 4);
            cp16(dst, Bgh + src);
            cp16(dst + 4096, Bgl + src);
        }
    };

    float acc[2][4][4] = {};
    int nT = Ksz / 32;

    loadStage(0, 0);
    asm volatile("cp.async.commit_group;" ::: "memory");
    loadStage(1, 1);
    asm volatile("cp.async.commit_group;" ::: "memory");

    for (int t = 0; t < nT; t++) {
        asm volatile("cp.async.wait_group 1;" ::: "memory");
        __syncthreads();

        if (t + 2 < nT) {
            loadStage(t + 2, (t + 2) % N_STAGES);
            asm volatile("cp.async.commit_group;" ::: "memory");
        } else {
            asm volatile("cp.async.commit_group;" ::: "memory");
        }

        unsigned* base = sm + (t % N_STAGES) * STG_U32;

        #pragma unroll
        for (int kk = 0; kk < 2; kk++) {
            unsigned afh[2][4], afl[2][4], bfh[4][2], bfl[4][2];
            #pragma unroll
            for (int mi = 0; mi < 2; mi++) {
                int off = ((wm * 2 + mi) * 2 + kk) * 128 + lane * 4;
                uint4 v = *(uint4*)(base + off);
                afh[mi][0] = v.x; afh[mi][1] = v.y; afh[mi][2] = v.z; afh[mi][3] = v.w;
                v = *(uint4*)(base + 2048 + off);
                afl[mi][0] = v.x; afl[mi][1] = v.y; afl[mi][2] = v.z; afl[mi][3] = v.w;
            }
            #pragma unroll
            for (int ni = 0; ni < 4; ni++) {
                int off = 4096 + (kk * 8 + wn * 4 + ni) * 64 + lane * 2;
                uint2 v = *(uint2*)(base + off);
                bfh[ni][0] = v.x; bfh[ni][1] = v.y;
                v = *(uint2*)(base + 1024 + off);
                bfl[ni][0] = v.x; bfl[ni][1] = v.y;
            }
            #pragma unroll
            for (int mi = 0; mi < 2; mi++)
                #pragma unroll
                for (int ni = 0; ni < 4; ni++) {
                    mma_bf16(acc[mi][ni], afl[mi], bfh[ni]);
                    mma_bf16(acc[mi][ni], afh[mi], bfl[ni]);
                    mma_bf16(acc[mi][ni], afh[mi], bfh[ni]);
                }
        }
    }
    asm volatile("cp.async.wait_group 0;" ::: "memory");

    // ---- epilogue ----
    float* Cb = C + (long)b * batchC;
    #pragma unroll
    for (int mi = 0; mi < 2; mi++) {
        #pragma unroll
        for (int ni = 0; ni < 4; ni++) {
            int r0 = rowBlk + wm * 32 + mi * 16 + gid;
            int c0 = colBlk + wn * 32 + ni * 8 + tig * 2;
            #pragma unroll
            for (int h = 0; h < 2; h++) {
                int r = r0 + h * 8;
                float v0 = acc[mi][ni][h * 2 + 0];
                float v1 = acc[mi][ni][h * 2 + 1];
                if (EPI == 1) {
                    float bias = sq[r];
                    float p0 = expf(v0 * PROJ_SCALE - bias) * RSQ_M;
                    float p1 = expf(v1 * PROJ_SCALE - bias) * RSQ_M;
                    unsigned hh, ll;
                    packpair(p0, p1, hh, ll);
                    long o = (long)r * (ldc / 2) + c0 / 2;
                    OH[o] = hh; OL[o] = ll;
                    if (OH2) {
                        int gg = (rowBlk >> 4) + wm * 2 + mi;
                        int ss = (colBlk >> 4) + wn * 2 + (ni >> 1);
                        long a = (((long)gg * SAout + ss) * 32 + gid * 4 + tig) * 4
                                 + (h + 2 * (ni & 1));
                        OH2[a] = hh; OL2[a] = ll;
                    }
                } else if (EPI == 2) {
                    long o = (long)r * ldc + c0;
                    atomicAdd(&Cb[o], v0);
                    atomicAdd(&Cb[o + 1], v1);
                } else {
                    float inv = 1.0f / den[b * Ln + r];
                    float fa0 = v0 * inv, fa1 = v1 * inv;
                    long go = (long)b * batchC + (long)r * ldc + c0;
                    C[go]     = content[go] + fa0;
                    C[go + 1] = content[go + 1] + fa1;
                    out2[go]     = fa0;
                    out2[go + 1] = fa1;
                }
            }
        }
    }
}

// Two shells: 2-CTA bound (proven win for phi GEMMs) and unconstrained.
template<int EPI>
__global__ void __launch_bounds__(256, 2)
tc_gemm2(const unsigned* __restrict__ Ah, const unsigned* __restrict__ Al,
         const unsigned* __restrict__ Bh, const unsigned* __restrict__ Bl,
         float* __restrict__ C, int Ksz, int SA, int Nt, int ldc, int SAout,
         long batchA, long batchB, long batchC, int splitK,
         const float* __restrict__ sq,
         unsigned* __restrict__ OH, unsigned* __restrict__ OL,
         unsigned* __restrict__ OH2, unsigned* __restrict__ OL2,
         const float* __restrict__ den, const float* __restrict__ content,
         float* __restrict__ out2)
{
    extern __shared__ __align__(16) unsigned sm[];
    gemm_body<EPI>(Ah, Al, Bh, Bl, C, Ksz, SA, Nt, ldc, SAout,
                   batchA, batchB, batchC, splitK, sq, OH, OL, OH2, OL2,
                   den, content, out2, sm);
}

template<int EPI>
__global__ void __launch_bounds__(256)
tc_gemm1(const unsigned* __restrict__ Ah, const unsigned* __restrict__ Al,
         const unsigned* __restrict__ Bh, const unsigned* __restrict__ Bl,
         float* __restrict__ C, int Ksz, int SA, int Nt, int ldc, int SAout,
         long batchA, long batchB, long batchC, int splitK,
         const float* __restrict__ sq,
         unsigned* __restrict__ OH, unsigned* __restrict__ OL,
         unsigned* __restrict__ OH2, unsigned* __restrict__ OL2,
         const float* __restrict__ den, const float* __restrict__ content,
         float* __restrict__ out2)
{
    extern __shared__ __align__(16) unsigned sm[];
    gemm_body<EPI>(Ah, Al, Bh, Bl, C, Ksz, SA, Nt, ldc, SAout,
                   batchA, batchB, batchC, splitK, sq, OH, OL, OH2, OL2,
                   den, content, out2, sm);
}

// ---------------------------------------------------------------------------
__global__ void den_kernel(const unsigned* __restrict__ ph, const unsigned* __restrict__ pl,
                           const float* __restrict__ Z, float* __restrict__ den)
{
    int row  = blockIdx.x * 8 + (threadIdx.x >> 5);
    int lane = threadIdx.x & 31;
    int b = row / Ln;
    uint4 h = ((const uint4*)(ph + (long)row * (Mf/2)))[lane];
    uint4 l = ((const uint4*)(pl + (long)row * (Mf/2)))[lane];
    const float* z = Z + b * Mf + lane * 8;
    unsigned hw[4] = {h.x, h.y, h.z, h.w};
    unsigned lw[4] = {l.x, l.y, l.z, l.w};
    float s = 0.f;
    #pragma unroll
    for (int j = 0; j < 4; j++) {
        s += (bfu((unsigned short)(hw[j] & 0xffff)) + bfu((unsigned short)(lw[j] & 0xffff))) * z[2*j];
        s += (bfu((unsigned short)(hw[j] >> 16))    + bfu((unsigned short)(lw[j] >> 16)))    * z[2*j+1];
    }
    #pragma unroll
    for (int o = 16; o; o >>= 1) s += __shfl_xor_sync(0xffffffffu, s, o);
    if (lane == 0) den[row] = s + 1e-8f;
}

// ---------------------------------------------------------------------------
#define SPLIT_S 4

extern "C" void kernel_launch(void* const* d_in, const int* in_sizes, int n_in,
                              void* d_out, int out_size)
{
    const float* content = (const float*)d_in[0];
    const float* style   = (const float*)d_in[1];
    const float* W       = (const float*)d_in[2];
    float* out = (float*)d_out;

    unsigned *cAh,*cAl,*sAh,*sAl,*wBh,*wBl,*spBh,*spBl,*pqh,*pql,*pqch,*pqcl,
             *pkh,*pkl,*pkTh,*pkTl,*sBh,*sBl;
    float *S, *Z, *den, *sqq, *sqk;
    cudaGetSymbolAddress((void**)&cAh, g_cA_h);   cudaGetSymbolAddress((void**)&cAl, g_cA_l);
    cudaGetSymbolAddress((void**)&sAh, g_sA_h);   cudaGetSymbolAddress((void**)&sAl, g_sA_l);
    cudaGetSymbolAddress((void**)&wBh, g_wB_h);   cudaGetSymbolAddress((void**)&wBl, g_wB_l);
    cudaGetSymbolAddress((void**)&spBh, g_spB_h); cudaGetSymbolAddress((void**)&spBl, g_spB_l);
    cudaGetSymbolAddress((void**)&pqh, g_pq_h);   cudaGetSymbolAddress((void**)&pql, g_pq_l);
    cudaGetSymbolAddress((void**)&pqch, g_pqc_h); cudaGetSymbolAddress((void**)&pqcl, g_pqc_l);
    cudaGetSymbolAddress((void**)&pkh, g_pk_h);   cudaGetSymbolAddress((void**)&pkl, g_pk_l);
    cudaGetSymbolAddress((void**)&pkTh, g_pkT_h); cudaGetSymbolAddress((void**)&pkTl, g_pkT_l);
    cudaGetSymbolAddress((void**)&sBh, g_sB_h);   cudaGetSymbolAddress((void**)&sBl, g_sB_l);
    cudaGetSymbolAddress((void**)&S,   g_S);
    cudaGetSymbolAddress((void**)&Z,   g_Z);
    cudaGetSymbolAddress((void**)&den, g_den);
    cudaGetSymbolAddress((void**)&sqq, g_sq_q);
    cudaGetSymbolAddress((void**)&sqk, g_sq_k);

    cudaFuncSetAttribute(tc_gemm2<1>, cudaFuncAttributeMaxDynamicSharedMemorySize, SMEM_BYTES);
    cudaFuncSetAttribute(tc_gemm1<2>, cudaFuncAttributeMaxDynamicSharedMemorySize, SMEM_BYTES);
    cudaFuncSetAttribute(tc_gemm1<3>, cudaFuncAttributeMaxDynamicSharedMemorySize, SMEM_BYTES);

    // 1) zero S, Z (Z accumulated by transpack)
    zero_kernel<<<(Bn * Mf * Dn) / 256, 256>>>(S, Z);

    // 2) sum-of-squares + canonical-A packs
    rowsumsq_pack<<<ROWS_Q / 16, 256>>>(content, sqq, cAh, cAl);
    rowsumsq_pack<<<ROWS_K / 16, 256>>>(style, sqk, sAh, sAl);

    // 3) canonical-B packs: W (gather form), style (coalesced form)
    packB_canon<<<(32 * 32) / 8, 256>>>(W, wBh, wBl, Dn, Mf, 0, 0);
    styleB_pack<<<ROWS_K / 16, 256>>>(style, spBh, spBl);

    // 4) phi_q = phi(content @ W): std + canonical outputs  (2-CTA variant)
    tc_gemm2<1><<<dim3(Mf/64, ROWS_Q/128, 1), 256, SMEM_BYTES>>>(
        cAh, cAl, wBh, wBl, nullptr, Dn, 32, Mf, Mf, 16,
        0, 0, 0, 1, sqq, pqh, pql, pqch, pqcl, nullptr, nullptr, nullptr);

    // 5) phi_k = phi(style @ W): std output only  (2-CTA variant)
    tc_gemm2<1><<<dim3(Mf/64, ROWS_K/128, 1), 256, SMEM_BYTES>>>(
        sAh, sAl, wBh, wBl, nullptr, Dn, 32, Mf, Mf, 0,
        0, 0, 0, 1, sqk, pkh, pkl, nullptr, nullptr, nullptr, nullptr, nullptr);

    // 6) transpose-pack phi_k -> canonical A (SA=512 per batch) + fused Z
    transpack<<<dim3(KLn/64, Mf/64, Bn), 256>>>(pkh, pkl, pkTh, pkTl, Z);

    // 7) S[b][m][d] = sum_kl phi_k^T * style  (split-K atomics, unconstrained)
    tc_gemm1<2><<<dim3(Dn/64, Mf/128, Bn * SPLIT_S), 256, SMEM_BYTES>>>(
        pkTh, pkTl, spBh, spBl, S, KLn/SPLIT_S, 512, Dn, Dn, 0,
        16L*512*128, (long)512*64*64, (long)Mf*Dn, SPLIT_S,
        nullptr, nullptr, nullptr, nullptr, nullptr, nullptr, nullptr, nullptr);

    // 8) canonical-B pack of S
    packB_canon<<<(Bn * 16 * 64) / 8, 256>>>(S, sBh, sBl, Mf, Dn,
                                             (long)Mf * Dn, (long)16 * 64 * 32);

    // 9) den
    den_kernel<<<ROWS_Q / 8, 256>>>(pqh, pql, Z, den);

    // 10) num GEMM fused final (unconstrained)
    tc_gemm1<3><<<dim3(Dn/64, Ln/128, Bn), 256, SMEM_BYTES>>>(
        pqch, pqcl, sBh, sBl, out, Mf, 16, Dn, Dn, 0,
        (long)(Ln/16)*16*128, (long)16*64*64, (long)Ln*Dn, 1,
        nullptr, nullptr, nullptr, nullptr, nullptr, den, content,
        out + (long)ROWS_Q * Dn);
}

// round 17
// speedup vs baseline: 1.0877x; 1.0375x over previous
#include <cuda_runtime.h>
#include <cuda_bf16.h>
#include <math.h>
#include <stdint.h>

// Problem constants (B=8, L=2048, D=512, K=4, m=256)
#define Bn 8
#define Ln 2048
#define Dn 512
#define Mf 256
#define KLn 8192
#define ROWS_Q 16384
#define ROWS_K 65536

// ===========================================================================
// Canonical fragment layouts (u32 = bf16 pair, low16 = even k):
//  A: element (row r, kpair kp):  g=r>>4, b=(r&15)>>3, gid=r&7,
//     s=kp>>3, tig=kp&3, hi=(kp>>2)&1, j=b+2*hi
//     u32 index = ((g*SA + s)*32 + gid*4 + tig)*4 + j          (SA = K/16)
//  B: element (kp, col n): s=kp>>3, tig=kp&3, j=(kp>>2)&1, h=n>>3, gid=n&7
//     u32 index = ((s*(N/8) + h)*32 + gid*4 + tig)*2 + j
// ===========================================================================

__device__ unsigned g_cA_h[(size_t)(ROWS_Q/16)*32*128];      // content A canon
__device__ unsigned g_cA_l[(size_t)(ROWS_Q/16)*32*128];
__device__ unsigned g_sA_h[(size_t)(ROWS_K/16)*32*128];      // style A canon
__device__ unsigned g_sA_l[(size_t)(ROWS_K/16)*32*128];
__device__ unsigned g_wB_h[(size_t)32*32*64];                // W B canon
__device__ unsigned g_wB_l[(size_t)32*32*64];
__device__ unsigned g_spB_h[(size_t)Bn*512*64*64];           // style B canon
__device__ unsigned g_spB_l[(size_t)Bn*512*64*64];
__device__ unsigned g_pqc_h[(size_t)(ROWS_Q/16)*16*128];     // phi_q A canon
__device__ unsigned g_pqc_l[(size_t)(ROWS_Q/16)*16*128];
__device__ unsigned g_pk_h[(size_t)ROWS_K*(Mf/2)];           // phi_k std
__device__ unsigned g_pk_l[(size_t)ROWS_K*(Mf/2)];
__device__ unsigned g_pkT_h[(size_t)Bn*16*512*128];          // phi_k^T A canon
__device__ unsigned g_pkT_l[(size_t)Bn*16*512*128];
__device__ unsigned g_sB_h[(size_t)Bn*16*64*64];             // S B canon
__device__ unsigned g_sB_l[(size_t)Bn*16*64*64];
__device__ float g_S[(size_t)Bn*Mf*Dn];
__device__ float g_Z[Bn*Mf];
__device__ float g_den[ROWS_Q];
__device__ float g_sq_q[ROWS_Q];
__device__ float g_sq_k[ROWS_K];

__device__ __constant__ float PROJ_SCALE = 0.21022410381342864f;  // 512^-0.25
__device__ __constant__ float SQ_SCALE   = 0.022097086912079608f; // 1/(2*sqrt(512))
__device__ __constant__ float RSQ_M      = 0.0625f;               // 256^-0.5

// ---------------- helpers ----------------------------------------------------
__device__ __forceinline__ uint32_t smem_addr(const void* p) {
    uint32_t a;
    asm("{ .reg .u64 t; cvta.to.shared.u64 t, %1; cvt.u32.u64 %0, t; }" : "=r"(a) : "l"(p));
    return a;
}
__device__ __forceinline__ void split1(float x, unsigned short& h, unsigned short& l) {
    __nv_bfloat16 hb = __float2bfloat16_rn(x);
    h = __bfloat16_as_ushort(hb);
    l = __bfloat16_as_ushort(__float2bfloat16_rn(x - __bfloat162float(hb)));
}
__device__ __forceinline__ float bfu(unsigned short u) {
    return __bfloat162float(__ushort_as_bfloat16(u));
}
__device__ __forceinline__ void packpair(float a, float b, unsigned& h, unsigned& l) {
    unsigned short ha, la, hb, lb;
    split1(a, ha, la); split1(b, hb, lb);
    h = (unsigned)ha | ((unsigned)hb << 16);
    l = (unsigned)la | ((unsigned)lb << 16);
}
__device__ __forceinline__ void cp16(uint32_t d, const void* g) {
    asm volatile("cp.async.cg.shared.global [%0], [%1], 16;" :: "r"(d), "l"(g));
}
__device__ __forceinline__ void mma_bf16(float c[4], const unsigned a[4], const unsigned b[2]) {
    asm volatile(
        "mma.sync.aligned.m16n8k16.row.col.f32.bf16.bf16.f32 "
        "{%0,%1,%2,%3}, {%4,%5,%6,%7}, {%8,%9}, {%0,%1,%2,%3};\n"
        : "+f"(c[0]), "+f"(c[1]), "+f"(c[2]), "+f"(c[3])
        : "r"(a[0]), "r"(a[1]), "r"(a[2]), "r"(a[3]), "r"(b[0]), "r"(b[1]));
}

// ---------------------------------------------------------------------------
// rowsumsq + canonical-A pack.  grid = rows/16, block = 256.
// ---------------------------------------------------------------------------
__global__ void rowsumsq_pack(const float* __restrict__ X, float* __restrict__ sq,
                              unsigned* __restrict__ OH, unsigned* __restrict__ OL)
{
    int g = blockIdx.x;
    int w = threadIdx.x >> 5;
    int s = threadIdx.x & 31;
    int r0 = g * 16 + w;
    int r1 = r0 + 8;

    float f0[16], f1[16];
    {
        const float4* p0 = (const float4*)(X + (long)r0 * Dn + s * 16);
        const float4* p1 = (const float4*)(X + (long)r1 * Dn + s * 16);
        #pragma unroll
        for (int i = 0; i < 4; i++) {
            float4 v = p0[i];
            f0[4*i] = v.x; f0[4*i+1] = v.y; f0[4*i+2] = v.z; f0[4*i+3] = v.w;
            v = p1[i];
            f1[4*i] = v.x; f1[4*i+1] = v.y; f1[4*i+2] = v.z; f1[4*i+3] = v.w;
        }
    }
    float s0 = 0.f, s1 = 0.f;
    #pragma unroll
    for (int i = 0; i < 16; i++) { s0 += f0[i]*f0[i]; s1 += f1[i]*f1[i]; }
    #pragma unroll
    for (int o = 16; o; o >>= 1) {
        s0 += __shfl_xor_sync(0xffffffffu, s0, o);
        s1 += __shfl_xor_sync(0xffffffffu, s1, o);
    }
    if (s == 0) { sq[r0] = s0 * SQ_SCALE; sq[r1] = s1 * SQ_SCALE; }

    unsigned wh[16], wl[16];
    #pragma unroll
    for (int tig = 0; tig < 4; tig++) {
        #pragma unroll
        for (int q = 0; q < 4; q++) {
            int t = tig + 4 * (q >> 1);
            const float* f = (q & 1) ? f1 : f0;
            packpair(f[2*t], f[2*t+1], wh[tig*4+q], wl[tig*4+q]);
        }
    }
    long base = (((long)g * 32 + s) * 32 + w * 4) * 4;
    #pragma unroll
    for (int i = 0; i < 4; i++) {
        *(uint4*)(OH + base + i * 4) = make_uint4(wh[4*i], wh[4*i+1], wh[4*i+2], wh[4*i+3]);
        *(uint4*)(OL + base + i * 4) = make_uint4(wl[4*i], wl[4*i+1], wl[4*i+2], wl[4*i+3]);
    }
}

// ---------------------------------------------------------------------------
// styleB_pack: canonical-B pack of style with coalesced reads AND writes.
// ---------------------------------------------------------------------------
__global__ void styleB_pack(const float* __restrict__ X,
                            unsigned* __restrict__ BH, unsigned* __restrict__ BL)
{
    int g = blockIdx.x;
    const float* tb = X + (long)g * 16 * Dn;
    int bb = g >> 9;
    long sL = g & 511;
    #pragma unroll
    for (int rep = 0; rep < 2; rep++) {
        int n = threadIdx.x + rep * 256;
        int hB = n >> 3, gidn = n & 7;
        unsigned bh[8], bl[8];
        #pragma unroll
        for (int t = 0; t < 8; t++)
            packpair(tb[(long)(2*t) * Dn + n], tb[(long)(2*t+1) * Dn + n], bh[t], bl[t]);
        long o = (long)bb * (512L*64*64) + ((sL * 64 + hB) * 32 + gidn * 4) * 2;
        *(uint4*)(BH + o)     = make_uint4(bh[0], bh[4], bh[1], bh[5]);
        *(uint4*)(BH + o + 4) = make_uint4(bh[2], bh[6], bh[3], bh[7]);
        *(uint4*)(BL + o)     = make_uint4(bl[0], bl[4], bl[1], bl[5]);
        *(uint4*)(BL + o + 4) = make_uint4(bl[2], bl[6], bl[3], bl[7]);
    }
}

// ---------------------------------------------------------------------------
// Canonical-B pack from fp32 [K][N] (batched). Used for W and S.
// ---------------------------------------------------------------------------
__global__ void packB_canon(const float* __restrict__ src,
                            unsigned* __restrict__ dh, unsigned* __restrict__ dl,
                            int K, int N, long srcBatch, long dstBatchU2)
{
    long blk = (long)blockIdx.x * 8 + (threadIdx.x >> 5);
    int lane = threadIdx.x & 31;
    int gid = lane >> 2, tig = lane & 3;
    long perBatch = (long)(K / 16) * (N / 8);
    int bb = (int)(blk / perBatch);
    long rem = blk % perBatch;
    int s = (int)(rem / (N / 8));
    int h = (int)(rem % (N / 8));
    int n = h * 8 + gid;
    const float* sb = src + (long)bb * srcBatch;
    unsigned h0, l0, h1, l1;
    {
        int r = 16 * s + 2 * tig;
        packpair(sb[(long)r * N + n], sb[(long)(r + 1) * N + n], h0, l0);
        packpair(sb[(long)(r + 8) * N + n], sb[(long)(r + 9) * N + n], h1, l1);
    }
    long u2 = (long)bb * dstBatchU2 + ((long)s * (N / 8) + h) * 32 + lane;
    ((uint2*)dh)[u2] = make_uint2(h0, h1);
    ((uint2*)dl)[u2] = make_uint2(l0, l1);
}

// ---------------------------------------------------------------------------
// transpose-pack phi_k std -> canonical-A [b][m][kl] (SA=512), with fused Z.
// ---------------------------------------------------------------------------
__global__ void transpack(const unsigned* __restrict__ sh_, const unsigned* __restrict__ sl_,
                          unsigned* __restrict__ dh, unsigned* __restrict__ dl,
                          float* __restrict__ Z)
{
    __shared__ unsigned Th[64][33], Tl[64][33];
    int tk = blockIdx.x, tm = blockIdx.y, bb = blockIdx.z;
    const unsigned* sh = sh_ + ((long)bb * KLn + tk * 64) * (Mf/2) + tm * 32;
    const unsigned* sl = sl_ + ((long)bb * KLn + tk * 64) * (Mf/2) + tm * 32;
    int r = threadIdx.x >> 3, c4 = (threadIdx.x & 7) * 4;
    {
        uint4 v = *(const uint4*)(sh + (long)r * (Mf/2) + c4);
        Th[r][c4] = v.x; Th[r][c4+1] = v.y; Th[r][c4+2] = v.z; Th[r][c4+3] = v.w;
        v = *(const uint4*)(sh + (long)(r + 32) * (Mf/2) + c4);
        Th[r+32][c4] = v.x; Th[r+32][c4+1] = v.y; Th[r+32][c4+2] = v.z; Th[r+32][c4+3] = v.w;
        v = *(const uint4*)(sl + (long)r * (Mf/2) + c4);
        Tl[r][c4] = v.x; Tl[r][c4+1] = v.y; Tl[r][c4+2] = v.z; Tl[r][c4+3] = v.w;
        v = *(const uint4*)(sl + (long)(r + 32) * (Mf/2) + c4);
        Tl[r+32][c4] = v.x; Tl[r+32][c4+1] = v.y; Tl[r+32][c4+2] = v.z; Tl[r+32][c4+3] = v.w;
    }
    __syncthreads();
    int m = threadIdx.x >> 2;
    int kj = (threadIdx.x & 3) * 8;
    int mp = m >> 1, pm = m & 1;
    unsigned oh[8], ol[8];
    float zsum = 0.f;
    #pragma unroll
    for (int j = 0; j < 8; j++) {
        int klp = kj + j;
        unsigned t0 = Th[2*klp][mp],   t1 = Th[2*klp+1][mp];
        unsigned u0 = Tl[2*klp][mp],   u1 = Tl[2*klp+1][mp];
        unsigned e0 = pm ? (t0 >> 16) : (t0 & 0xffff);
        unsigned e1 = pm ? (t1 >> 16) : (t1 & 0xffff);
        oh[j] = e0 | (e1 << 16);
        unsigned f0 = pm ? (u0 >> 16) : (u0 & 0xffff);
        unsigned f1 = pm ? (u1 >> 16) : (u1 & 0xffff);
        ol[j] = f0 | (f1 << 16);
        zsum += bfu((unsigned short)e0) + bfu((unsigned short)e1)
              + bfu((unsigned short)f0) + bfu((unsigned short)f1);
    }
    int mg = tm * 64 + m;
    atomicAdd(&Z[bb * Mf + mg], zsum);
    int g = mg >> 4, b_ = (mg & 15) >> 3, gidw = mg & 7;
    int sS = (tk * 32 + kj) >> 3;
    long base = (long)bb * (16L * 512 * 128) + (((long)g * 512 + sS) * 32 + gidw * 4) * 4;
    #pragma unroll
    for (int j = 0; j < 8; j++) {
        int tig = j & 3, hi = j >> 2;
        long a = base + tig * 4 + b_ + 2 * hi;
        dh[a] = oh[j]; dl[a] = ol[j];
    }
}

__global__ void zero_kernel(float* __restrict__ S, float* __restrict__ Z,
                            float* __restrict__ den)
{
    long i = (long)blockIdx.x * 256 + threadIdx.x;
    if (i < (long)Bn * Mf * Dn) S[i] = 0.f;
    if (i < Bn * Mf)            Z[i] = 0.f;
    if (i < ROWS_Q)             den[i] = 1e-8f;
}

// ---------------------------------------------------------------------------
// Canonical-layout bf16x2-compensated GEMM (round-12 proven core),
// 3-stage cp.async pipeline, ONE __syncthreads per iteration.
//  Stage (u32): AH 0..2047 | AL 2048..4095 | BH 4096..5119 | BL 5120..6143
//  EPI=1: phi epilogue. Optional std store (OH), optional canonical store
//         (OH2), optional fused den accumulation (den = Z input, out2 = den).
//  EPI=2: atomicAdd fp32 into C (split-K)
//  EPI=3: fused final
// ---------------------------------------------------------------------------
#define STG_U32 6144
#define N_STAGES 3
#define SMEM_BYTES (N_STAGES * STG_U32 * 4)

template<int EPI>
__global__ void __launch_bounds__(256)
tc_gemm(const unsigned* __restrict__ Ah, const unsigned* __restrict__ Al,
        const unsigned* __restrict__ Bh, const unsigned* __restrict__ Bl,
        float* __restrict__ C, int Ksz, int SA, int Nt, int ldc, int SAout,
        long batchA, long batchB, long batchC, int splitK,
        const float* __restrict__ sq,
        unsigned* __restrict__ OH, unsigned* __restrict__ OL,
        unsigned* __restrict__ OH2, unsigned* __restrict__ OL2,
        const float* __restrict__ den, const float* __restrict__ content,
        float* __restrict__ out2)
{
    extern __shared__ __align__(16) unsigned sm[];

    int bz = blockIdx.z;
    int b  = bz / splitK;
    int sp = bz % splitK;
    int sBeg = sp * (Ksz / 16);

    const unsigned* Agh = Ah + (long)b * batchA;
    const unsigned* Agl = Al + (long)b * batchA;
    const unsigned* Bgh = Bh + (long)b * batchB;
    const unsigned* Bgl = Bl + (long)b * batchB;

    int rowBlk = blockIdx.y * 128;
    int colBlk = blockIdx.x * 64;
    int gA = rowBlk >> 4;
    int hA = colBlk >> 3;
    int tid = threadIdx.x, wid = tid >> 5, lane = tid & 31;
    int gid = lane >> 2, tig = lane & 3;
    int wm = wid >> 1, wn = wid & 1;

    auto loadStage = [&](int t, int st) {
        unsigned* base = sm + st * STG_U32;
        int s0 = sBeg + 2 * t;
        {
            int blk = tid >> 4;
            int gl = blk >> 1, sl = blk & 1;
            long src = (((long)(gA + gl)) * SA + (s0 + sl)) * 128 + (tid & 15) * 8;
            uint32_t dst = smem_addr(base + blk * 128 + (tid & 15) * 8);
            cp16(dst,      Agh + src);
            cp16(dst + 16, Agh + src + 4);
            cp16(dst + 8192,      Agl + src);
            cp16(dst + 8192 + 16, Agl + src + 4);
        }
        {
            int blk = tid >> 4;
            int sl = blk >> 3, hl = blk & 7;
            long src = ((long)(s0 + sl)) * (Nt / 8) * 64 + (long)(hA + hl) * 64 + (tid & 15) * 4;
            uint32_t dst = smem_addr(base + 4096 + blk * 64 + (tid & 15) * 4);
            cp16(dst, Bgh + src);
            cp16(dst + 4096, Bgl + src);
        }
    };

    float acc[2][4][4] = {};
    int nT = Ksz / 32;

    loadStage(0, 0);
    asm volatile("cp.async.commit_group;" ::: "memory");
    loadStage(1, 1);
    asm volatile("cp.async.commit_group;" ::: "memory");

    for (int t = 0; t < nT; t++) {
        asm volatile("cp.async.wait_group 1;" ::: "memory");
        __syncthreads();

        if (t + 2 < nT) {
            loadStage(t + 2, (t + 2) % N_STAGES);
            asm volatile("cp.async.commit_group;" ::: "memory");
        } else {
            asm volatile("cp.async.commit_group;" ::: "memory");
        }

        unsigned* base = sm + (t % N_STAGES) * STG_U32;

        #pragma unroll
        for (int kk = 0; kk < 2; kk++) {
            unsigned afh[2][4], afl[2][4], bfh[4][2], bfl[4][2];
            #pragma unroll
            for (int mi = 0; mi < 2; mi++) {
                int off = ((wm * 2 + mi) * 2 + kk) * 128 + lane * 4;
                uint4 v = *(uint4*)(base + off);
                afh[mi][0] = v.x; afh[mi][1] = v.y; afh[mi][2] = v.z; afh[mi][3] = v.w;
                v = *(uint4*)(base + 2048 + off);
                afl[mi][0] = v.x; afl[mi][1] = v.y; afl[mi][2] = v.z; afl[mi][3] = v.w;
            }
            #pragma unroll
            for (int ni = 0; ni < 4; ni++) {
                int off = 4096 + (kk * 8 + wn * 4 + ni) * 64 + lane * 2;
                uint2 v = *(uint2*)(base + off);
                bfh[ni][0] = v.x; bfh[ni][1] = v.y;
                v = *(uint2*)(base + 1024 + off);
                bfl[ni][0] = v.x; bfl[ni][1] = v.y;
            }
            #pragma unroll
            for (int mi = 0; mi < 2; mi++)
                #pragma unroll
                for (int ni = 0; ni < 4; ni++) {
                    mma_bf16(acc[mi][ni], afl[mi], bfh[ni]);
                    mma_bf16(acc[mi][ni], afh[mi], bfl[ni]);
                    mma_bf16(acc[mi][ni], afh[mi], bfh[ni]);
                }
        }
    }
    asm volatile("cp.async.wait_group 0;" ::: "memory");

    // ---- epilogue ----
    float* Cb = C + (long)b * batchC;
    float dpart[2][2] = {};
    const float* Zrow = (EPI == 1 && out2) ? (den + (rowBlk >> 11) * Mf) : nullptr;
    #pragma unroll
    for (int mi = 0; mi < 2; mi++) {
        #pragma unroll
        for (int ni = 0; ni < 4; ni++) {
            int r0 = rowBlk + wm * 32 + mi * 16 + gid;
            int c0 = colBlk + wn * 32 + ni * 8 + tig * 2;
            #pragma unroll
            for (int h = 0; h < 2; h++) {
                int r = r0 + h * 8;
                float v0 = acc[mi][ni][h * 2 + 0];
                float v1 = acc[mi][ni][h * 2 + 1];
                if (EPI == 1) {
                    float bias = sq[r];
                    float p0 = expf(v0 * PROJ_SCALE - bias) * RSQ_M;
                    float p1 = expf(v1 * PROJ_SCALE - bias) * RSQ_M;
                    unsigned hh, ll;
                    packpair(p0, p1, hh, ll);
                    if (OH) {
                        long o = (long)r * (ldc / 2) + c0 / 2;
                        OH[o] = hh; OL[o] = ll;
                    }
                    if (OH2) {
                        int gg = (rowBlk >> 4) + wm * 2 + mi;
                        int ss = (colBlk >> 4) + wn * 2 + (ni >> 1);
                        long a = (((long)gg * SAout + ss) * 32 + gid * 4 + tig) * 4
                                 + (h + 2 * (ni & 1));
                        OH2[a] = hh; OL2[a] = ll;
                    }
                    if (Zrow)
                        dpart[mi][h] += p0 * Zrow[c0] + p1 * Zrow[c0 + 1];
                } else if (EPI == 2) {
                    long o = (long)r * ldc + c0;
                    atomicAdd(&Cb[o], v0);
                    atomicAdd(&Cb[o + 1], v1);
                } else {
                    float inv = 1.0f / den[b * Ln + r];
                    float fa0 = v0 * inv, fa1 = v1 * inv;
                    long go = (long)b * batchC + (long)r * ldc + c0;
                    C[go]     = content[go] + fa0;
                    C[go + 1] = content[go + 1] + fa1;
                    out2[go]     = fa0;
                    out2[go + 1] = fa1;
                }
            }
        }
    }
    if (EPI == 1 && out2) {
        #pragma unroll
        for (int mi = 0; mi < 2; mi++)
            #pragma unroll
            for (int h = 0; h < 2; h++)
                atomicAdd(&out2[rowBlk + wm * 32 + mi * 16 + gid + h * 8],
                          dpart[mi][h]);
    }
}

// ---------------------------------------------------------------------------
#define SPLIT_S 4

extern "C" void kernel_launch(void* const* d_in, const int* in_sizes, int n_in,
                              void* d_out, int out_size)
{
    const float* content = (const float*)d_in[0];
    const float* style   = (const float*)d_in[1];
    const float* W       = (const float*)d_in[2];
    float* out = (float*)d_out;

    unsigned *cAh,*cAl,*sAh,*sAl,*wBh,*wBl,*spBh,*spBl,*pqch,*pqcl,
             *pkh,*pkl,*pkTh,*pkTl,*sBh,*sBl;
    float *S, *Z, *den, *sqq, *sqk;
    cudaGetSymbolAddress((void**)&cAh, g_cA_h);   cudaGetSymbolAddress((void**)&cAl, g_cA_l);
    cudaGetSymbolAddress((void**)&sAh, g_sA_h);   cudaGetSymbolAddress((void**)&sAl, g_sA_l);
    cudaGetSymbolAddress((void**)&wBh, g_wB_h);   cudaGetSymbolAddress((void**)&wBl, g_wB_l);
    cudaGetSymbolAddress((void**)&spBh, g_spB_h); cudaGetSymbolAddress((void**)&spBl, g_spB_l);
    cudaGetSymbolAddress((void**)&pqch, g_pqc_h); cudaGetSymbolAddress((void**)&pqcl, g_pqc_l);
    cudaGetSymbolAddress((void**)&pkh, g_pk_h);   cudaGetSymbolAddress((void**)&pkl, g_pk_l);
    cudaGetSymbolAddress((void**)&pkTh, g_pkT_h); cudaGetSymbolAddress((void**)&pkTl, g_pkT_l);
    cudaGetSymbolAddress((void**)&sBh, g_sB_h);   cudaGetSymbolAddress((void**)&sBl, g_sB_l);
    cudaGetSymbolAddress((void**)&S,   g_S);
    cudaGetSymbolAddress((void**)&Z,   g_Z);
    cudaGetSymbolAddress((void**)&den, g_den);
    cudaGetSymbolAddress((void**)&sqq, g_sq_q);
    cudaGetSymbolAddress((void**)&sqk, g_sq_k);

    cudaFuncSetAttribute(tc_gemm<1>, cudaFuncAttributeMaxDynamicSharedMemorySize, SMEM_BYTES);
    cudaFuncSetAttribute(tc_gemm<2>, cudaFuncAttributeMaxDynamicSharedMemorySize, SMEM_BYTES);
    cudaFuncSetAttribute(tc_gemm<3>, cudaFuncAttributeMaxDynamicSharedMemorySize, SMEM_BYTES);

    // 1) zero S, Z; init den = eps (Z by transpack, den by phi_q epilogue)
    zero_kernel<<<(Bn * Mf * Dn) / 256, 256>>>(S, Z, den);

    // 2) sum-of-squares + canonical-A packs
    rowsumsq_pack<<<ROWS_Q / 16, 256>>>(content, sqq, cAh, cAl);
    rowsumsq_pack<<<ROWS_K / 16, 256>>>(style, sqk, sAh, sAl);

    // 3) canonical-B packs: W (gather form), style (coalesced form)
    packB_canon<<<(32 * 32) / 8, 256>>>(W, wBh, wBl, Dn, Mf, 0, 0);
    styleB_pack<<<ROWS_K / 16, 256>>>(style, spBh, spBl);

    // 4) phi_k = phi(style @ W): std output only
    tc_gemm<1><<<dim3(Mf/64, ROWS_K/128, 1), 256, SMEM_BYTES>>>(
        sAh, sAl, wBh, wBl, nullptr, Dn, 32, Mf, Mf, 0,
        0, 0, 0, 1, sqk, pkh, pkl, nullptr, nullptr, nullptr, nullptr, nullptr);

    // 5) transpose-pack phi_k -> canonical A (SA=512 per batch) + fused Z
    transpack<<<dim3(KLn/64, Mf/64, Bn), 256>>>(pkh, pkl, pkTh, pkTl, Z);

    // 6) phi_q = phi(content @ W): canonical output + FUSED den (needs Z)
    tc_gemm<1><<<dim3(Mf/64, ROWS_Q/128, 1), 256, SMEM_BYTES>>>(
        cAh, cAl, wBh, wBl, nullptr, Dn, 32, Mf, Mf, 16,
        0, 0, 0, 1, sqq, nullptr, nullptr, pqch, pqcl, Z, nullptr, den);

    // 7) S[b][m][d] = sum_kl phi_k^T * style  (split-K atomics)
    tc_gemm<2><<<dim3(Dn/64, Mf/128, Bn * SPLIT_S), 256, SMEM_BYTES>>>(
        pkTh, pkTl, spBh, spBl, S, KLn/SPLIT_S, 512, Dn, Dn, 0,
        16L*512*128, (long)512*64*64, (long)Mf*Dn, SPLIT_S,
        nullptr, nullptr, nullptr, nullptr, nullptr, nullptr, nullptr, nullptr);

    // 8) canonical-B pack of S
    packB_canon<<<(Bn * 16 * 64) / 8, 256>>>(S, sBh, sBl, Mf, Dn,
                                             (long)Mf * Dn, (long)16 * 64 * 32);

    // 9) num GEMM fused final
    tc_gemm<3><<<dim3(Dn/64, Ln/128, Bn), 256, SMEM_BYTES>>>(
        pqch, pqcl, sBh, sBl, out, Mf, 16, Dn, Dn, 0,
        (long)(Ln/16)*16*128, (long)16*64*64, (long)Ln*Dn, 1,
        nullptr, nullptr, nullptr, nullptr, nullptr, den, content,
        out + (long)ROWS_Q * Dn);
}